// round 13
// baseline (speedup 1.0000x reference)
#include <cuda_runtime.h>
#include <cuda_bf16.h>
#include <cstdint>

#define B_     16
#define N_     256
#define DIM_   768
#define HEADS_ 12
#define DHEAD_ 64
#define BH_    192
#define MAREA  2025
#define MPAD   2048
#define ROWS_  4096
#define K3     2304

typedef __nv_bfloat16 bf16;

// ---------------- device global scratch ----------------
__device__ float g_biasqkv[K3];
__device__ bf16  g_x_hi[ROWS_*DIM_],   g_x_lo[ROWS_*DIM_];
__device__ bf16  g_wqkv_hi[DIM_*K3],   g_wqkv_lo[DIM_*K3];
__device__ bf16  g_wT_hi[3*DIM_*DIM_], g_wT_lo[3*DIM_*DIM_];
__device__ bf16  g_woT_hi[DIM_*DIM_],  g_woT_lo[DIM_*DIM_];
__device__ bf16  g_weffT_hi[K3*DIM_],  g_weffT_lo[K3*DIM_];
__device__ float g_qkvh_f[(size_t)ROWS_*K3];
__device__ bf16  g_qkvh_hi[(size_t)ROWS_*K3], g_qkvh_lo[(size_t)ROWS_*K3];
__device__ bf16  g_ka_hi[(size_t)BH_*MPAD*DHEAD_], g_ka_lo[(size_t)BH_*MPAD*DHEAD_];
__device__ bf16  g_va_hi[(size_t)BH_*MPAD*DHEAD_], g_va_lo[(size_t)BH_*MPAD*DHEAD_];
__device__ bf16  g_attn_hi[(size_t)ROWS_*DIM_],    g_attn_lo[(size_t)ROWS_*DIM_];
__device__ int4   g_aidx[MPAD];
__device__ float2 g_ascale[MPAD];
__device__ float g_Opart[(size_t)2*ROWS_*DIM_];
__device__ float g_lpart[2*ROWS_*HEADS_];

// ---------------- helpers ----------------
__device__ __forceinline__ uint32_t smem_u32(const void* p) {
    uint32_t a;
    asm("{ .reg .u64 t; cvta.to.shared.u64 t, %1; cvt.u32.u64 %0, t; }" : "=r"(a) : "l"(p));
    return a;
}
__device__ __forceinline__ uint32_t packhi2(float x, float y) {
    __nv_bfloat162 t = __floats2bfloat162_rn(x, y);
    return *(uint32_t*)&t;
}
__device__ __forceinline__ uint32_t packlo2(float x, float y, uint32_t hp) {
    __nv_bfloat162 h = *(__nv_bfloat162*)&hp;
    __nv_bfloat162 t = __floats2bfloat162_rn(x - __bfloat162float(h.x),
                                             y - __bfloat162float(h.y));
    return *(uint32_t*)&t;
}

#define MMA16(d, a, b0, b1) \
    asm volatile("mma.sync.aligned.m16n8k16.row.col.f32.bf16.bf16.f32 " \
        "{%0,%1,%2,%3}, {%4,%5,%6,%7}, {%8,%9}, {%0,%1,%2,%3};" \
        : "+f"((d)[0]), "+f"((d)[1]), "+f"((d)[2]), "+f"((d)[3]) \
        : "r"((a)[0]), "r"((a)[1]), "r"((a)[2]), "r"((a)[3]), "r"(b0), "r"(b1))

__device__ __forceinline__ void ldsm4(uint32_t addr, uint32_t& r0, uint32_t& r1,
                                      uint32_t& r2, uint32_t& r3) {
    asm volatile("ldmatrix.sync.aligned.m8n8.x4.shared.b16 {%0,%1,%2,%3}, [%4];"
                 : "=r"(r0), "=r"(r1), "=r"(r2), "=r"(r3) : "r"(addr));
}
__device__ __forceinline__ void ldsm4t(uint32_t addr, uint32_t& r0, uint32_t& r1,
                                       uint32_t& r2, uint32_t& r3) {
    asm volatile("ldmatrix.sync.aligned.m8n8.x4.trans.shared.b16 {%0,%1,%2,%3}, [%4];"
                 : "=r"(r0), "=r"(r1), "=r"(r2), "=r"(r3) : "r"(addr));
}
__device__ __forceinline__ void cpasync16(uint32_t saddr, const void* g) {
    asm volatile("cp.async.cg.shared.global [%0], [%1], 16;" :: "r"(saddr), "l"(g));
}
#define CP_COMMIT() asm volatile("cp.async.commit_group;" ::: "memory")
#define CP_WAIT0()  asm volatile("cp.async.wait_group 0;" ::: "memory")
#define CP_WAIT1()  asm volatile("cp.async.wait_group 1;" ::: "memory")

// ---------------- fused prep kernel (vectorized) ---------------------------
#define NB_CONVX4 3072
#define NB_CONVW4 1728
#define NB_CONVT  2304
#define NB_TBL    8
__global__ __launch_bounds__(256)
void prep_kernel(const float* __restrict__ x, const float* __restrict__ w_qkv,
                 const float* __restrict__ w_q, const float* __restrict__ w_k,
                 const float* __restrict__ w_v, const float* __restrict__ w_o,
                 const float* __restrict__ bq, const float* __restrict__ bk,
                 const float* __restrict__ bv) {
    __shared__ float tile[32][33];
    int bx = blockIdx.x, t = threadIdx.x;
    if (bx < NB_CONVX4 + NB_CONVW4) {
        const float* src;
        bf16 *hi, *lo;
        int i;
        if (bx < NB_CONVX4) {
            i = (bx * 256 + t) * 4;
            src = x; hi = g_x_hi; lo = g_x_lo;
        } else {
            i = ((bx - NB_CONVX4) * 256 + t) * 4;
            src = w_qkv; hi = g_wqkv_hi; lo = g_wqkv_lo;
        }
        float4 v = *(const float4*)(src + i);
        uint32_t h01 = packhi2(v.x, v.y), h23 = packhi2(v.z, v.w);
        uint32_t l01 = packlo2(v.x, v.y, h01), l23 = packlo2(v.z, v.w, h23);
        *(uint2*)(hi + i) = make_uint2(h01, h23);
        *(uint2*)(lo + i) = make_uint2(l01, l23);
    } else if (bx < NB_CONVX4 + NB_CONVW4 + NB_CONVT) {
        int id = bx - (NB_CONVX4 + NB_CONVW4);
        int seg = id / 576, rem = id % 576;
        int c0 = (rem % 24) * 32, r0 = (rem / 24) * 32;
        const float* src = (seg == 0) ? w_q : (seg == 1) ? w_k : (seg == 2) ? w_v : w_o;
        bf16* hi = (seg < 3) ? (g_wT_hi + (size_t)seg * DIM_ * DIM_) : g_woT_hi;
        bf16* lo = (seg < 3) ? (g_wT_lo + (size_t)seg * DIM_ * DIM_) : g_woT_lo;
        int tx = t & 31, ty = t >> 5;
#pragma unroll
        for (int i = 0; i < 4; ++i)
            tile[ty + i * 8][tx] = src[(size_t)(r0 + ty + i * 8) * DIM_ + c0 + tx];
        __syncthreads();
#pragma unroll
        for (int i = 0; i < 4; ++i) {
            float v = tile[tx][ty + i * 8];
            size_t o = (size_t)(c0 + ty + i * 8) * DIM_ + r0 + tx;
            bf16 h = __float2bfloat16(v);
            hi[o] = h;
            lo[o] = __float2bfloat16(v - __bfloat162float(h));
        }
    } else if (bx < NB_CONVX4 + NB_CONVW4 + NB_CONVT + NB_TBL) {
        int m = (bx - (NB_CONVX4 + NB_CONVW4 + NB_CONVT)) * 256 + t;
        const int cnts[9] = {256, 240, 224, 240, 225, 210, 224, 210, 196};
        int iA = 0, iB = 0, iC = 0, iD = 0;
        float sk = 0.f, sv = 0.f;
        if (m < MAREA) {
            int rem = m, seg = 0;
            while (rem >= cnts[seg]) { rem -= cnts[seg]; ++seg; }
            int ah = seg / 3 + 1, aw = seg % 3 + 1;
            int w = 17 - aw;
            int y0 = rem / w, x0 = rem % w;
            iA = (y0 + ah) * 17 + x0 + aw; iB = y0 * 17 + x0 + aw;
            iC = (y0 + ah) * 17 + x0;      iD = y0 * 17 + x0;
            sk = 1.f / (float)(ah * aw);   sv = 1.f;
        }
        g_aidx[m] = make_int4(iA, iB, iC, iD);
        g_ascale[m] = make_float2(sk, sv);
    } else {
        int idx = (bx - (NB_CONVX4 + NB_CONVW4 + NB_CONVT + NB_TBL)) * 256 + t;
        int seg = idx / 768;
        const float* s = (seg == 0) ? bq : (seg == 1) ? bk : bv;
        g_biasqkv[idx] = s[idx % 768];
    }
}

// ---------------- 128x128 warp-MMA GEMM, BK=32, 2 CTAs/SM -----------------
#define GSTG 40960
__global__ __launch_bounds__(256, 2)
void gemm128_kernel(const bf16* __restrict__ Ah, const bf16* __restrict__ Al, int lda,
                    const bf16* __restrict__ Bh, const bf16* __restrict__ Bl, int ldb,
                    float* __restrict__ Cf, bf16* __restrict__ Chi, bf16* __restrict__ Clo,
                    int ldc, int K, const float* __restrict__ bias,
                    int sAz, int sBz, int sCz, int qkvMode) {
    extern __shared__ char smem[];
    uint32_t sb = smem_u32(smem);
    int z = blockIdx.z;
    Ah += (size_t)z * sAz; Al += (size_t)z * sAz;
    Bh += (size_t)z * sBz; Bl += (size_t)z * sBz;
    if (Cf)  Cf  += (size_t)z * sCz;
    if (Chi) { Chi += (size_t)z * sCz; Clo += (size_t)z * sCz; }

    int tid = threadIdx.x, lane = tid & 31, wid = tid >> 5;
    int g = lane >> 2, tig = lane & 3;
    int wm = (wid >> 1) * 32, wn = (wid & 1) * 64;
    int m0 = blockIdx.y * 128, n0 = blockIdx.x * 128;
    int r16 = lane & 15, koff = (lane >> 4) * 8;

    bool doF = Cf  && (qkvMode == 0 || n0 >= 768);
    bool doH = Chi && (qkvMode == 0 || n0 < 768);

    float acc[2][8][4];
#pragma unroll
    for (int mt = 0; mt < 2; ++mt)
#pragma unroll
        for (int nt = 0; nt < 8; ++nt)
#pragma unroll
            for (int i = 0; i < 4; ++i) acc[mt][nt][i] = 0.f;

    auto load_chunk = [&](int kc, int s) {
        uint32_t st = sb + s * GSTG;
#pragma unroll
        for (int it = 0; it < 2; ++it) {
            int idx = tid + it * 256;
            int row = idx >> 2, seg8 = (idx & 3) * 8;
            uint32_t so = row * 80 + seg8 * 2;
            size_t ga = (size_t)(m0 + row) * lda + kc + seg8;
            size_t gb = (size_t)(n0 + row) * ldb + kc + seg8;
            cpasync16(st +         so, Ah + ga);
            cpasync16(st + 10240 + so, Al + ga);
            cpasync16(st + 20480 + so, Bh + gb);
            cpasync16(st + 30720 + so, Bl + gb);
        }
    };

    int nch = K / 32;
    load_chunk(0, 0);
    CP_COMMIT();
    for (int c = 0; c < nch; ++c) {
        int s = c & 1;
        if (c + 1 < nch) { load_chunk((c + 1) * 32, s ^ 1); CP_COMMIT(); CP_WAIT1(); }
        else CP_WAIT0();
        __syncthreads();
        uint32_t st = sb + s * GSTG;
#pragma unroll
        for (int ks = 0; ks < 2; ++ks) {
            uint32_t ah[2][4], al[2][4];
#pragma unroll
            for (int mt = 0; mt < 2; ++mt) {
                uint32_t aadr = st + (wm + mt * 16 + r16) * 80 + (ks * 16 + koff) * 2;
                ldsm4(aadr,         ah[mt][0], ah[mt][1], ah[mt][2], ah[mt][3]);
                ldsm4(aadr + 10240, al[mt][0], al[mt][1], al[mt][2], al[mt][3]);
            }
#pragma unroll
            for (int ntp = 0; ntp < 4; ++ntp) {
                uint32_t badr = st + 20480 + (wn + ntp * 16 + r16) * 80 + (ks * 16 + koff) * 2;
                uint32_t bh4[4], bl4[4];
                ldsm4(badr,         bh4[0], bh4[1], bh4[2], bh4[3]);
                ldsm4(badr + 10240, bl4[0], bl4[1], bl4[2], bl4[3]);
#pragma unroll
                for (int half = 0; half < 2; ++half) {
                    int nt = 2 * ntp + half;
                    uint32_t bh0 = bh4[half], bh1 = bh4[half + 2];
                    uint32_t bl0 = bl4[half], bl1 = bl4[half + 2];
#pragma unroll
                    for (int mt = 0; mt < 2; ++mt) {
                        MMA16(acc[mt][nt], ah[mt], bh0, bh1);
                        MMA16(acc[mt][nt], ah[mt], bl0, bl1);
                        MMA16(acc[mt][nt], al[mt], bh0, bh1);
                    }
                }
            }
        }
        __syncthreads();
    }
#pragma unroll
    for (int mt = 0; mt < 2; ++mt)
#pragma unroll
        for (int nt = 0; nt < 8; ++nt) {
            int row = m0 + wm + mt * 16 + g;
            int col = n0 + wn + nt * 8 + 2 * tig;
            float v0 = acc[mt][nt][0], v1 = acc[mt][nt][1];
            float v2 = acc[mt][nt][2], v3 = acc[mt][nt][3];
            if (bias) {
                float b0v = bias[col], b1v = bias[col + 1];
                v0 += b0v; v1 += b1v; v2 += b0v; v3 += b1v;
            }
            if (doF) {
                *(float2*)(Cf + (size_t)row * ldc + col)       = make_float2(v0, v1);
                *(float2*)(Cf + (size_t)(row + 8) * ldc + col) = make_float2(v2, v3);
            }
            if (doH) {
                uint32_t h01 = packhi2(v0, v1), h23 = packhi2(v2, v3);
                *(uint32_t*)(Chi + (size_t)row * ldc + col)       = h01;
                *(uint32_t*)(Chi + (size_t)(row + 8) * ldc + col) = h23;
                *(uint32_t*)(Clo + (size_t)row * ldc + col)       = packlo2(v0, v1, h01);
                *(uint32_t*)(Clo + (size_t)(row + 8) * ldc + col) = packlo2(v2, v3, h23);
            }
        }
}

// ---------------- area pooling: both SATs built, single m-loop ------------
__global__ __launch_bounds__(256)
void pool_kernel() {
    int bh = blockIdx.x, cbase = blockIdx.y * 16;
    int b = bh / HEADS_, h = bh % HEADS_;
    __shared__ float sat[2][16][289];
    int t = threadIdx.x;

    // phase 1: row prefix sums for BOTH sources (512 tasks)
#pragma unroll
    for (int p = 0; p < 2; ++p) {
        const float* base = g_qkvh_f + (size_t)(b * N_) * K3 + (p ? 2 * DIM_ : DIM_)
                          + h * DHEAD_ + cbase;
        int ch = t & 15, row = t >> 4;
        if (row == 0)
#pragma unroll
            for (int x = 0; x < 17; ++x) sat[p][ch][x] = 0.f;
        sat[p][ch][(row + 1) * 17] = 0.f;
        float vals[16];
#pragma unroll
        for (int x = 0; x < 16; ++x)
            vals[x] = base[(size_t)(row * 16 + x) * K3 + ch];
        float acc = 0.f;
#pragma unroll
        for (int x = 0; x < 16; ++x) {
            acc += vals[x];
            sat[p][ch][(row + 1) * 17 + x + 1] = acc;
        }
    }
    __syncthreads();
    // phase 2: column prefix for both SATs
#pragma unroll
    for (int p = 0; p < 2; ++p) {
        int ch = t >> 4, col = (t & 15) + 1;
        float acc = 0.f;
#pragma unroll
        for (int y = 1; y <= 16; ++y) {
            acc += sat[p][ch][y * 17 + col];
            sat[p][ch][y * 17 + col] = acc;
        }
    }
    __syncthreads();
    // phase 3: single m-loop, table read once, emits K and V together
    int sub = t & 1;
    for (int m = t >> 1; m < MPAD; m += 128) {
        int4 ix = g_aidx[m];
        float2 sc2 = g_ascale[m];
        bf16 khv[8], klv[8], vhv[8], vlv[8];
#pragma unroll
        for (int c = 0; c < 8; ++c) {
            int ch = sub * 8 + c;
            float sK = (sat[0][ch][ix.x] - sat[0][ch][ix.y]
                      - sat[0][ch][ix.z] + sat[0][ch][ix.w]) * sc2.x;
            float sV = (sat[1][ch][ix.x] - sat[1][ch][ix.y]
                      - sat[1][ch][ix.z] + sat[1][ch][ix.w]) * sc2.y;
            khv[c] = __float2bfloat16(sK);
            klv[c] = __float2bfloat16(sK - __bfloat162float(khv[c]));
            vhv[c] = __float2bfloat16(sV);
            vlv[c] = __float2bfloat16(sV - __bfloat162float(vhv[c]));
        }
        size_t o = ((size_t)bh * MPAD + m) * DHEAD_ + cbase + sub * 8;
        *(uint4*)(g_ka_hi + o) = *(uint4*)khv;
        *(uint4*)(g_ka_lo + o) = *(uint4*)klv;
        *(uint4*)(g_va_hi + o) = *(uint4*)vhv;
        *(uint4*)(g_va_lo + o) = *(uint4*)vlv;
    }
}

// ---------------- attention: split halves, Q fragments hoisted ------------
#define ASTG 36864
#define AQOF 36864
#define AHALF (MPAD / 2)
__global__ __launch_bounds__(256, 2)
void attn_kernel() {
    extern __shared__ char smem[];
    uint32_t sb = smem_u32(smem);
    int tid = threadIdx.x, lane = tid & 31, wid = tid >> 5;
    int g = lane >> 2, tig = lane & 3;
    int wm = wid * 16;
    int bh = blockIdx.x, q0 = blockIdx.y * 128, z = blockIdx.z;
    int a0 = z * AHALF;
    int b = bh / HEADS_, h = bh % HEADS_;
    int r16 = lane & 15, koff = (lane >> 4) * 8;

    bf16* Qs = (bf16*)smem;
#pragma unroll
    for (int it = 0; it < 4; ++it) {
        int idx = tid + it * 256;
        int row = idx >> 3, seg = (idx & 7) * 8;
        size_t src = (size_t)(b * N_ + q0 + row) * K3 + h * 64 + seg;
        *(uint4*)(Qs + row * 72 + seg)        = *(const uint4*)(g_qkvh_hi + src);
        *(uint4*)(Qs + 9216 + row * 72 + seg) = *(const uint4*)(g_qkvh_lo + src);
    }

    const bf16* kaH = g_ka_hi + (size_t)bh * MPAD * 64 + (size_t)a0 * 64;
    const bf16* kaL = g_ka_lo + (size_t)bh * MPAD * 64 + (size_t)a0 * 64;
    const bf16* vaH = g_va_hi + (size_t)bh * MPAD * 64 + (size_t)a0 * 64;
    const bf16* vaL = g_va_lo + (size_t)bh * MPAD * 64 + (size_t)a0 * 64;

    auto load_tile = [&](int t, int s) {
        uint32_t st = sb + AQOF + s * ASTG;
#pragma unroll
        for (int it = 0; it < 2; ++it) {
            int idx = tid + it * 256;
            int row = idx >> 3, seg = (idx & 7) * 8;
            uint32_t so = row * 144 + seg * 2;
            size_t gk = (size_t)(t * 64 + row) * 64 + seg;
            cpasync16(st +         so, kaH + gk);
            cpasync16(st +  9216 + so, kaL + gk);
            cpasync16(st + 18432 + so, vaH + gk);
            cpasync16(st + 27648 + so, vaL + gk);
        }
    };

    load_tile(0, 0);
    CP_COMMIT();
    __syncthreads();   // Q stores visible

    // hoisted Q fragments (constant across tiles)
    uint32_t qh[4][4], ql[4][4];
#pragma unroll
    for (int ks = 0; ks < 4; ++ks) {
        uint32_t qadr = sb + (wm + r16) * 144 + (ks * 16 + koff) * 2;
        ldsm4(qadr,         qh[ks][0], qh[ks][1], qh[ks][2], qh[ks][3]);
        ldsm4(qadr + 18432, ql[ks][0], ql[ks][1], ql[ks][2], ql[ks][3]);
    }

    float accO[8][4];
#pragma unroll
    for (int nt = 0; nt < 8; ++nt)
#pragma unroll
        for (int i = 0; i < 4; ++i) accO[nt][i] = 0.f;
    float lsum[2] = {0.f, 0.f};

    const int NT = AHALF / 64;  // 16
    for (int t = 0; t < NT; ++t) {
        int s = t & 1;
        if (t + 1 < NT) { load_tile(t + 1, s ^ 1); CP_COMMIT(); CP_WAIT1(); }
        else CP_WAIT0();
        __syncthreads();
        uint32_t st = sb + AQOF + s * ASTG;

        // ---- QK ----
        float sc[8][4];
#pragma unroll
        for (int nt = 0; nt < 8; ++nt)
#pragma unroll
            for (int i = 0; i < 4; ++i) sc[nt][i] = 0.f;
#pragma unroll
        for (int ks = 0; ks < 4; ++ks) {
#pragma unroll
            for (int ntp = 0; ntp < 4; ++ntp) {
                uint32_t kadr = st + (ntp * 16 + r16) * 144 + (ks * 16 + koff) * 2;
                uint32_t kh4[4], kl4[4];
                ldsm4(kadr,        kh4[0], kh4[1], kh4[2], kh4[3]);
                ldsm4(kadr + 9216, kl4[0], kl4[1], kl4[2], kl4[3]);
#pragma unroll
                for (int half = 0; half < 2; ++half) {
                    int nt = 2 * ntp + half;
                    uint32_t b0h = kh4[half], b1h = kh4[half + 2];
                    uint32_t b0l = kl4[half], b1l = kl4[half + 2];
                    MMA16(sc[nt], qh[ks], b0h, b1h);
                    MMA16(sc[nt], qh[ks], b0l, b1l);
                    MMA16(sc[nt], ql[ks], b0h, b1h);
                }
            }
        }

        // ---- softmax ----
        bool need_mask = (a0 + t * 64 + 64) > MAREA;
        if (need_mask) {
#pragma unroll
            for (int nt = 0; nt < 8; ++nt) {
                int cb = a0 + t * 64 + nt * 8 + 2 * tig;
                float p0 = (cb     < MAREA) ? __expf(sc[nt][0]) : 0.f;
                float p1 = (cb + 1 < MAREA) ? __expf(sc[nt][1]) : 0.f;
                float p2 = (cb     < MAREA) ? __expf(sc[nt][2]) : 0.f;
                float p3 = (cb + 1 < MAREA) ? __expf(sc[nt][3]) : 0.f;
                sc[nt][0] = p0; sc[nt][1] = p1; sc[nt][2] = p2; sc[nt][3] = p3;
                lsum[0] += p0 + p1;
                lsum[1] += p2 + p3;
            }
        } else {
#pragma unroll
            for (int nt = 0; nt < 8; ++nt) {
                float p0 = __expf(sc[nt][0]);
                float p1 = __expf(sc[nt][1]);
                float p2 = __expf(sc[nt][2]);
                float p3 = __expf(sc[nt][3]);
                sc[nt][0] = p0; sc[nt][1] = p1; sc[nt][2] = p2; sc[nt][3] = p3;
                lsum[0] += p0 + p1;
                lsum[1] += p2 + p3;
            }
        }

        // ---- PV ----
#pragma unroll
        for (int kk = 0; kk < 4; ++kk) {
            uint32_t pah[4], pal[4];
            pah[0] = packhi2(sc[2 * kk][0],     sc[2 * kk][1]);
            pah[1] = packhi2(sc[2 * kk][2],     sc[2 * kk][3]);
            pah[2] = packhi2(sc[2 * kk + 1][0], sc[2 * kk + 1][1]);
            pah[3] = packhi2(sc[2 * kk + 1][2], sc[2 * kk + 1][3]);
            pal[0] = packlo2(sc[2 * kk][0],     sc[2 * kk][1],     pah[0]);
            pal[1] = packlo2(sc[2 * kk][2],     sc[2 * kk][3],     pah[1]);
            pal[2] = packlo2(sc[2 * kk + 1][0], sc[2 * kk + 1][1], pah[2]);
            pal[3] = packlo2(sc[2 * kk + 1][2], sc[2 * kk + 1][3], pah[3]);
#pragma unroll
            for (int ntp = 0; ntp < 4; ++ntp) {
                uint32_t vadr = st + 18432 + (kk * 16 + r16) * 144 + (ntp * 16 + koff) * 2;
                uint32_t vh4[4], vl4[4];
                ldsm4t(vadr,        vh4[0], vh4[1], vh4[2], vh4[3]);
                ldsm4t(vadr + 9216, vl4[0], vl4[1], vl4[2], vl4[3]);
#pragma unroll
                for (int half = 0; half < 2; ++half) {
                    int nt = 2 * ntp + half;
                    uint32_t b0h = vh4[half * 2], b1h = vh4[half * 2 + 1];
                    uint32_t b0l = vl4[half * 2], b1l = vl4[half * 2 + 1];
                    MMA16(accO[nt], pah, b0h, b1h);
                    MMA16(accO[nt], pah, b0l, b1l);
                    MMA16(accO[nt], pal, b0h, b1h);
                }
            }
        }
        __syncthreads();
    }

    // ---- write unnormalized partials ----
#pragma unroll
    for (int r = 0; r < 2; ++r) {
        lsum[r] += __shfl_xor_sync(0xFFFFFFFF, lsum[r], 1);
        lsum[r] += __shfl_xor_sync(0xFFFFFFFF, lsum[r], 2);
    }
    int row0 = b * N_ + q0 + wm + g;
    size_t obase = (size_t)z * ROWS_ * DIM_;
    size_t orow0 = obase + (size_t)row0 * DIM_ + h * 64;
    size_t orow1 = obase + (size_t)(row0 + 8) * DIM_ + h * 64;
#pragma unroll
    for (int nt = 0; nt < 8; ++nt) {
        int cc = nt * 8 + 2 * tig;
        *(float2*)(g_Opart + orow0 + cc) = make_float2(accO[nt][0], accO[nt][1]);
        *(float2*)(g_Opart + orow1 + cc) = make_float2(accO[nt][2], accO[nt][3]);
    }
    if (tig == 0) {
        g_lpart[z * ROWS_ * HEADS_ + row0 * HEADS_ + h]       = lsum[0];
        g_lpart[z * ROWS_ * HEADS_ + (row0 + 8) * HEADS_ + h] = lsum[1];
    }
}

// ---------------- combine: (O0+O1)/(l0+l1) -> attn hi/lo ------------------
__global__ __launch_bounds__(256)
void combine_kernel() {
    int i = blockIdx.x * 256 + threadIdx.x;
    int e = i * 2;
    int row = e / DIM_, col = e % DIM_;
    int h = col >> 6;
    float l = g_lpart[row * HEADS_ + h] + g_lpart[ROWS_ * HEADS_ + row * HEADS_ + h];
    float inv = 1.f / l;
    float2 a = *(float2*)(g_Opart + e);
    float2 bb = *(float2*)(g_Opart + (size_t)ROWS_ * DIM_ + e);
    float o0 = (a.x + bb.x) * inv, o1 = (a.y + bb.y) * inv;
    uint32_t h01 = packhi2(o0, o1);
    *(uint32_t*)(g_attn_hi + e) = h01;
    *(uint32_t*)(g_attn_lo + e) = packlo2(o0, o1, h01);
}

// ---------------- launch ---------------------------------------------------
extern "C" void kernel_launch(void* const* d_in, const int* in_sizes, int n_in,
                              void* d_out, int out_size) {
    const float* x     = (const float*)d_in[0];
    const float* w_qkv = (const float*)d_in[1];
    const float* w_q   = (const float*)d_in[2];
    const float* b_q   = (const float*)d_in[3];
    const float* w_k   = (const float*)d_in[4];
    const float* b_k   = (const float*)d_in[5];
    const float* w_v   = (const float*)d_in[6];
    const float* b_v   = (const float*)d_in[7];
    const float* w_o   = (const float*)d_in[8];
    const float* b_o   = (const float*)d_in[9];
    float* out = (float*)d_out;

    cudaFuncSetAttribute(gemm128_kernel, cudaFuncAttributeMaxDynamicSharedMemorySize, 2 * GSTG);
    cudaFuncSetAttribute(attn_kernel,    cudaFuncAttributeMaxDynamicSharedMemorySize, AQOF + 2 * ASTG);

    bf16 *x_hi, *x_lo, *wqkv_hi, *wqkv_lo, *wT_hi, *wT_lo, *woT_hi, *woT_lo;
    bf16 *weffT_hi, *weffT_lo, *qkvh_hi, *qkvh_lo, *attn_hi, *attn_lo;
    float *qkvh_f, *biasqkv;
    cudaGetSymbolAddress((void**)&x_hi, g_x_hi);       cudaGetSymbolAddress((void**)&x_lo, g_x_lo);
    cudaGetSymbolAddress((void**)&wqkv_hi, g_wqkv_hi); cudaGetSymbolAddress((void**)&wqkv_lo, g_wqkv_lo);
    cudaGetSymbolAddress((void**)&wT_hi, g_wT_hi);     cudaGetSymbolAddress((void**)&wT_lo, g_wT_lo);
    cudaGetSymbolAddress((void**)&woT_hi, g_woT_hi);   cudaGetSymbolAddress((void**)&woT_lo, g_woT_lo);
    cudaGetSymbolAddress((void**)&weffT_hi, g_weffT_hi); cudaGetSymbolAddress((void**)&weffT_lo, g_weffT_lo);
    cudaGetSymbolAddress((void**)&qkvh_f, g_qkvh_f);
    cudaGetSymbolAddress((void**)&qkvh_hi, g_qkvh_hi); cudaGetSymbolAddress((void**)&qkvh_lo, g_qkvh_lo);
    cudaGetSymbolAddress((void**)&attn_hi, g_attn_hi); cudaGetSymbolAddress((void**)&attn_lo, g_attn_lo);
    cudaGetSymbolAddress((void**)&biasqkv, g_biasqkv);

    // 1. fused prep
    prep_kernel<<<NB_CONVX4 + NB_CONVW4 + NB_CONVT + NB_TBL + 9, 256>>>(
        x, w_qkv, w_q, w_k, w_v, w_o, b_q, b_k, b_v);

    // 2. compose W_eff^T
    {
        dim3 g(6, 6, 3);
        gemm128_kernel<<<g, 256, 2 * GSTG>>>(
            wT_hi, wT_lo, DIM_, wqkv_hi, wqkv_lo, K3,
            nullptr, weffT_hi, weffT_lo, DIM_, DIM_, nullptr,
            DIM_ * DIM_, DIM_, DIM_ * DIM_, 0);
    }

    // 3. qh|kh|vh = x @ W_eff + bias
    {
        dim3 g(K3 / 128, ROWS_ / 128, 1);
        gemm128_kernel<<<g, 256, 2 * GSTG>>>(x_hi, x_lo, DIM_, weffT_hi, weffT_lo, DIM_,
                                             qkvh_f, qkvh_hi, qkvh_lo, K3, DIM_, biasqkv,
                                             0, 0, 0, 1);
    }

    // 4. area pooling (fused passes; ncu-captured launch)
    {
        dim3 g(BH_, 4);
        pool_kernel<<<g, 256>>>();
    }

    // 5. attention
    {
        dim3 g(BH_, 2, 2);
        attn_kernel<<<g, 256, AQOF + 2 * ASTG>>>();
    }

    // 6. combine partials
    combine_kernel<<<ROWS_ * DIM_ / 512, 256>>>();

    // 7. out = attn @ w_o + b_o
    {
        dim3 g(DIM_ / 128, ROWS_ / 128, 1);
        gemm128_kernel<<<g, 256, 2 * GSTG>>>(attn_hi, attn_lo, DIM_, woT_hi, woT_lo, DIM_,
                                             out, nullptr, nullptr, DIM_, DIM_, b_o,
                                             0, 0, 0, 0);
    }
}

// round 14
// speedup vs baseline: 1.0238x; 1.0238x over previous
#include <cuda_runtime.h>
#include <cuda_bf16.h>
#include <cstdint>

#define B_     16
#define N_     256
#define DIM_   768
#define HEADS_ 12
#define DHEAD_ 64
#define BH_    192
#define MAREA  2025
#define MPAD   2048
#define ROWS_  4096
#define K3     2304

typedef __nv_bfloat16 bf16;

// ---------------- device global scratch ----------------
__device__ float g_biasqkv[K3];
__device__ bf16  g_x_hi[ROWS_*DIM_],   g_x_lo[ROWS_*DIM_];
__device__ bf16  g_wqkv_hi[DIM_*K3],   g_wqkv_lo[DIM_*K3];
__device__ bf16  g_wT_hi[3*DIM_*DIM_], g_wT_lo[3*DIM_*DIM_];
__device__ bf16  g_woT_hi[DIM_*DIM_],  g_woT_lo[DIM_*DIM_];
__device__ bf16  g_weffT_hi[K3*DIM_],  g_weffT_lo[K3*DIM_];
__device__ float g_qkvh_f[(size_t)ROWS_*K3];
__device__ bf16  g_qkvh_hi[(size_t)ROWS_*K3], g_qkvh_lo[(size_t)ROWS_*K3];
__device__ bf16  g_ka_hi[(size_t)BH_*MPAD*DHEAD_], g_ka_lo[(size_t)BH_*MPAD*DHEAD_];
__device__ bf16  g_va_hi[(size_t)BH_*MPAD*DHEAD_], g_va_lo[(size_t)BH_*MPAD*DHEAD_];
__device__ bf16  g_attn_hi[(size_t)ROWS_*DIM_],    g_attn_lo[(size_t)ROWS_*DIM_];
__device__ float g_Opart[(size_t)2*ROWS_*DIM_];
__device__ float g_lpart[2*ROWS_*HEADS_];

// ---------------- helpers ----------------
__device__ __forceinline__ uint32_t smem_u32(const void* p) {
    uint32_t a;
    asm("{ .reg .u64 t; cvta.to.shared.u64 t, %1; cvt.u32.u64 %0, t; }" : "=r"(a) : "l"(p));
    return a;
}
__device__ __forceinline__ uint32_t packhi2(float x, float y) {
    __nv_bfloat162 t = __floats2bfloat162_rn(x, y);
    return *(uint32_t*)&t;
}
__device__ __forceinline__ uint32_t packlo2(float x, float y, uint32_t hp) {
    __nv_bfloat162 h = *(__nv_bfloat162*)&hp;
    __nv_bfloat162 t = __floats2bfloat162_rn(x - __bfloat162float(h.x),
                                             y - __bfloat162float(h.y));
    return *(uint32_t*)&t;
}

#define MMA16(d, a, b0, b1) \
    asm volatile("mma.sync.aligned.m16n8k16.row.col.f32.bf16.bf16.f32 " \
        "{%0,%1,%2,%3}, {%4,%5,%6,%7}, {%8,%9}, {%0,%1,%2,%3};" \
        : "+f"((d)[0]), "+f"((d)[1]), "+f"((d)[2]), "+f"((d)[3]) \
        : "r"((a)[0]), "r"((a)[1]), "r"((a)[2]), "r"((a)[3]), "r"(b0), "r"(b1))

__device__ __forceinline__ void ldsm4(uint32_t addr, uint32_t& r0, uint32_t& r1,
                                      uint32_t& r2, uint32_t& r3) {
    asm volatile("ldmatrix.sync.aligned.m8n8.x4.shared.b16 {%0,%1,%2,%3}, [%4];"
                 : "=r"(r0), "=r"(r1), "=r"(r2), "=r"(r3) : "r"(addr));
}
__device__ __forceinline__ void ldsm4t(uint32_t addr, uint32_t& r0, uint32_t& r1,
                                       uint32_t& r2, uint32_t& r3) {
    asm volatile("ldmatrix.sync.aligned.m8n8.x4.trans.shared.b16 {%0,%1,%2,%3}, [%4];"
                 : "=r"(r0), "=r"(r1), "=r"(r2), "=r"(r3) : "r"(addr));
}
__device__ __forceinline__ void cpasync16(uint32_t saddr, const void* g) {
    asm volatile("cp.async.cg.shared.global [%0], [%1], 16;" :: "r"(saddr), "l"(g));
}
#define CP_COMMIT() asm volatile("cp.async.commit_group;" ::: "memory")
#define CP_WAIT0()  asm volatile("cp.async.wait_group 0;" ::: "memory")
#define CP_WAIT1()  asm volatile("cp.async.wait_group 1;" ::: "memory")

// ---------------- fused prep kernel (vectorized) ---------------------------
#define NB_CONVX4 3072
#define NB_CONVW4 1728
#define NB_CONVT  2304
__global__ __launch_bounds__(256)
void prep_kernel(const float* __restrict__ x, const float* __restrict__ w_qkv,
                 const float* __restrict__ w_q, const float* __restrict__ w_k,
                 const float* __restrict__ w_v, const float* __restrict__ w_o,
                 const float* __restrict__ bq, const float* __restrict__ bk,
                 const float* __restrict__ bv) {
    __shared__ float tile[32][33];
    int bx = blockIdx.x, t = threadIdx.x;
    if (bx < NB_CONVX4 + NB_CONVW4) {
        const float* src;
        bf16 *hi, *lo;
        int i;
        if (bx < NB_CONVX4) {
            i = (bx * 256 + t) * 4;
            src = x; hi = g_x_hi; lo = g_x_lo;
        } else {
            i = ((bx - NB_CONVX4) * 256 + t) * 4;
            src = w_qkv; hi = g_wqkv_hi; lo = g_wqkv_lo;
        }
        float4 v = *(const float4*)(src + i);
        uint32_t h01 = packhi2(v.x, v.y), h23 = packhi2(v.z, v.w);
        uint32_t l01 = packlo2(v.x, v.y, h01), l23 = packlo2(v.z, v.w, h23);
        *(uint2*)(hi + i) = make_uint2(h01, h23);
        *(uint2*)(lo + i) = make_uint2(l01, l23);
    } else if (bx < NB_CONVX4 + NB_CONVW4 + NB_CONVT) {
        int id = bx - (NB_CONVX4 + NB_CONVW4);
        int seg = id / 576, rem = id % 576;
        int c0 = (rem % 24) * 32, r0 = (rem / 24) * 32;
        const float* src = (seg == 0) ? w_q : (seg == 1) ? w_k : (seg == 2) ? w_v : w_o;
        bf16* hi = (seg < 3) ? (g_wT_hi + (size_t)seg * DIM_ * DIM_) : g_woT_hi;
        bf16* lo = (seg < 3) ? (g_wT_lo + (size_t)seg * DIM_ * DIM_) : g_woT_lo;
        int tx = t & 31, ty = t >> 5;
#pragma unroll
        for (int i = 0; i < 4; ++i)
            tile[ty + i * 8][tx] = src[(size_t)(r0 + ty + i * 8) * DIM_ + c0 + tx];
        __syncthreads();
#pragma unroll
        for (int i = 0; i < 4; ++i) {
            float v = tile[tx][ty + i * 8];
            size_t o = (size_t)(c0 + ty + i * 8) * DIM_ + r0 + tx;
            bf16 h = __float2bfloat16(v);
            hi[o] = h;
            lo[o] = __float2bfloat16(v - __bfloat162float(h));
        }
    } else {
        int idx = (bx - (NB_CONVX4 + NB_CONVW4 + NB_CONVT)) * 256 + t;
        int seg = idx / 768;
        const float* s = (seg == 0) ? bq : (seg == 1) ? bk : bv;
        g_biasqkv[idx] = s[idx % 768];
    }
}

// ---------------- 128x128 warp-MMA GEMM, BK=32, 2 CTAs/SM -----------------
#define GSTG 40960
__global__ __launch_bounds__(256, 2)
void gemm128_kernel(const bf16* __restrict__ Ah, const bf16* __restrict__ Al, int lda,
                    const bf16* __restrict__ Bh, const bf16* __restrict__ Bl, int ldb,
                    float* __restrict__ Cf, bf16* __restrict__ Chi, bf16* __restrict__ Clo,
                    int ldc, int K, const float* __restrict__ bias,
                    int sAz, int sBz, int sCz, int qkvMode) {
    extern __shared__ char smem[];
    uint32_t sb = smem_u32(smem);
    int z = blockIdx.z;
    Ah += (size_t)z * sAz; Al += (size_t)z * sAz;
    Bh += (size_t)z * sBz; Bl += (size_t)z * sBz;
    if (Cf)  Cf  += (size_t)z * sCz;
    if (Chi) { Chi += (size_t)z * sCz; Clo += (size_t)z * sCz; }

    int tid = threadIdx.x, lane = tid & 31, wid = tid >> 5;
    int g = lane >> 2, tig = lane & 3;
    int wm = (wid >> 1) * 32, wn = (wid & 1) * 64;
    int m0 = blockIdx.y * 128, n0 = blockIdx.x * 128;
    int r16 = lane & 15, koff = (lane >> 4) * 8;

    bool doF = Cf  && (qkvMode == 0 || n0 >= 768);
    bool doH = Chi && (qkvMode == 0 || n0 < 768);

    float acc[2][8][4];
#pragma unroll
    for (int mt = 0; mt < 2; ++mt)
#pragma unroll
        for (int nt = 0; nt < 8; ++nt)
#pragma unroll
            for (int i = 0; i < 4; ++i) acc[mt][nt][i] = 0.f;

    auto load_chunk = [&](int kc, int s) {
        uint32_t st = sb + s * GSTG;
#pragma unroll
        for (int it = 0; it < 2; ++it) {
            int idx = tid + it * 256;
            int row = idx >> 2, seg8 = (idx & 3) * 8;
            uint32_t so = row * 80 + seg8 * 2;
            size_t ga = (size_t)(m0 + row) * lda + kc + seg8;
            size_t gb = (size_t)(n0 + row) * ldb + kc + seg8;
            cpasync16(st +         so, Ah + ga);
            cpasync16(st + 10240 + so, Al + ga);
            cpasync16(st + 20480 + so, Bh + gb);
            cpasync16(st + 30720 + so, Bl + gb);
        }
    };

    int nch = K / 32;
    load_chunk(0, 0);
    CP_COMMIT();
    for (int c = 0; c < nch; ++c) {
        int s = c & 1;
        if (c + 1 < nch) { load_chunk((c + 1) * 32, s ^ 1); CP_COMMIT(); CP_WAIT1(); }
        else CP_WAIT0();
        __syncthreads();
        uint32_t st = sb + s * GSTG;
#pragma unroll
        for (int ks = 0; ks < 2; ++ks) {
            uint32_t ah[2][4], al[2][4];
#pragma unroll
            for (int mt = 0; mt < 2; ++mt) {
                uint32_t aadr = st + (wm + mt * 16 + r16) * 80 + (ks * 16 + koff) * 2;
                ldsm4(aadr,         ah[mt][0], ah[mt][1], ah[mt][2], ah[mt][3]);
                ldsm4(aadr + 10240, al[mt][0], al[mt][1], al[mt][2], al[mt][3]);
            }
#pragma unroll
            for (int ntp = 0; ntp < 4; ++ntp) {
                uint32_t badr = st + 20480 + (wn + ntp * 16 + r16) * 80 + (ks * 16 + koff) * 2;
                uint32_t bh4[4], bl4[4];
                ldsm4(badr,         bh4[0], bh4[1], bh4[2], bh4[3]);
                ldsm4(badr + 10240, bl4[0], bl4[1], bl4[2], bl4[3]);
#pragma unroll
                for (int half = 0; half < 2; ++half) {
                    int nt = 2 * ntp + half;
                    uint32_t bh0 = bh4[half], bh1 = bh4[half + 2];
                    uint32_t bl0 = bl4[half], bl1 = bl4[half + 2];
#pragma unroll
                    for (int mt = 0; mt < 2; ++mt) {
                        MMA16(acc[mt][nt], ah[mt], bh0, bh1);
                        MMA16(acc[mt][nt], ah[mt], bl0, bl1);
                        MMA16(acc[mt][nt], al[mt], bh0, bh1);
                    }
                }
            }
        }
        __syncthreads();
    }
#pragma unroll
    for (int mt = 0; mt < 2; ++mt)
#pragma unroll
        for (int nt = 0; nt < 8; ++nt) {
            int row = m0 + wm + mt * 16 + g;
            int col = n0 + wn + nt * 8 + 2 * tig;
            float v0 = acc[mt][nt][0], v1 = acc[mt][nt][1];
            float v2 = acc[mt][nt][2], v3 = acc[mt][nt][3];
            if (bias) {
                float b0v = bias[col], b1v = bias[col + 1];
                v0 += b0v; v1 += b1v; v2 += b0v; v3 += b1v;
            }
            if (doF) {
                *(float2*)(Cf + (size_t)row * ldc + col)       = make_float2(v0, v1);
                *(float2*)(Cf + (size_t)(row + 8) * ldc + col) = make_float2(v2, v3);
            }
            if (doH) {
                uint32_t h01 = packhi2(v0, v1), h23 = packhi2(v2, v3);
                *(uint32_t*)(Chi + (size_t)row * ldc + col)       = h01;
                *(uint32_t*)(Chi + (size_t)(row + 8) * ldc + col) = h23;
                *(uint32_t*)(Clo + (size_t)row * ldc + col)       = packlo2(v0, v1, h01);
                *(uint32_t*)(Clo + (size_t)(row + 8) * ldc + col) = packlo2(v2, v3, h23);
            }
        }
}

// ---------------- area pooling: R10 version (inline decode, fastest) ------
__global__ __launch_bounds__(256)
void pool_kernel() {
    int bh = blockIdx.x, cbase = blockIdx.y * 16;
    int b = bh / HEADS_, h = bh % HEADS_;
    __shared__ float sat[16][289];
    int t = threadIdx.x;
    const int cnts[9] = {256, 240, 224, 240, 225, 210, 224, 210, 196};

    for (int pass = 0; pass < 2; ++pass) {
        const float* base = g_qkvh_f + (size_t)(b * N_) * K3 + (pass ? 2 * DIM_ : DIM_)
                          + h * DHEAD_ + cbase;
        {
            int ch = t & 15, row = t >> 4;
            if (row == 0)
#pragma unroll
                for (int x = 0; x < 17; ++x) sat[ch][x] = 0.f;
            sat[ch][(row + 1) * 17] = 0.f;
            float vals[16];
#pragma unroll
            for (int x = 0; x < 16; ++x)
                vals[x] = base[(size_t)(row * 16 + x) * K3 + ch];
            float acc = 0.f;
#pragma unroll
            for (int x = 0; x < 16; ++x) {
                acc += vals[x];
                sat[ch][(row + 1) * 17 + x + 1] = acc;
            }
        }
        __syncthreads();
        {
            int ch = t >> 4, col = (t & 15) + 1;
            float acc = 0.f;
#pragma unroll
            for (int y = 1; y <= 16; ++y) {
                acc += sat[ch][y * 17 + col];
                sat[ch][y * 17 + col] = acc;
            }
        }
        __syncthreads();
        int sub = t & 1;
        for (int m = t >> 1; m < MPAD; m += 128) {
            float scale = 0.f;
            int y0 = 0, x0 = 0, ah = 1, aw = 1;
            bool valid = (m < MAREA);
            if (valid) {
                int rem = m, seg = 0;
                while (rem >= cnts[seg]) { rem -= cnts[seg]; ++seg; }
                ah = seg / 3 + 1; aw = seg % 3 + 1;
                int w = 17 - aw;
                y0 = rem / w; x0 = rem % w;
                scale = (pass == 0) ? 1.f / (float)(ah * aw) : 1.f;
            }
            int iA = (y0 + ah) * 17 + x0 + aw, iB = y0 * 17 + x0 + aw;
            int iC = (y0 + ah) * 17 + x0,      iD = y0 * 17 + x0;
            bf16 hv[8], lv[8];
#pragma unroll
            for (int c = 0; c < 8; ++c) {
                int ch = sub * 8 + c;
                float s = 0.f;
                if (valid)
                    s = (sat[ch][iA] - sat[ch][iB] - sat[ch][iC] + sat[ch][iD]) * scale;
                hv[c] = __float2bfloat16(s);
                lv[c] = __float2bfloat16(s - __bfloat162float(hv[c]));
            }
            size_t o = ((size_t)bh * MPAD + m) * DHEAD_ + cbase + sub * 8;
            if (pass == 0) {
                *(uint4*)(g_ka_hi + o) = *(uint4*)hv;
                *(uint4*)(g_ka_lo + o) = *(uint4*)lv;
            } else {
                *(uint4*)(g_va_hi + o) = *(uint4*)hv;
                *(uint4*)(g_va_lo + o) = *(uint4*)lv;
            }
        }
        __syncthreads();
    }
}

// ---------------- attention: split halves, bh-major grid for L2 reuse -----
#define ASTG 36864
#define AQOF 36864
#define AHALF (MPAD / 2)
__global__ __launch_bounds__(256, 2)
void attn_kernel() {
    extern __shared__ char smem[];
    uint32_t sb = smem_u32(smem);
    int tid = threadIdx.x, lane = tid & 31, wid = tid >> 5;
    int g = lane >> 2, tig = lane & 3;
    int wm = wid * 16;
    // grid (4, 192): x packs (qtile, z); same-bh CTAs are launch-adjacent.
    int bh = blockIdx.y;
    int q0 = (blockIdx.x >> 1) * 128;
    int z = blockIdx.x & 1;
    int a0 = z * AHALF;
    int b = bh / HEADS_, h = bh % HEADS_;
    int r16 = lane & 15, koff = (lane >> 4) * 8;

    bf16* Qs = (bf16*)smem;
#pragma unroll
    for (int it = 0; it < 4; ++it) {
        int idx = tid + it * 256;
        int row = idx >> 3, seg = (idx & 7) * 8;
        size_t src = (size_t)(b * N_ + q0 + row) * K3 + h * 64 + seg;
        *(uint4*)(Qs + row * 72 + seg)        = *(const uint4*)(g_qkvh_hi + src);
        *(uint4*)(Qs + 9216 + row * 72 + seg) = *(const uint4*)(g_qkvh_lo + src);
    }

    const bf16* kaH = g_ka_hi + (size_t)bh * MPAD * 64 + (size_t)a0 * 64;
    const bf16* kaL = g_ka_lo + (size_t)bh * MPAD * 64 + (size_t)a0 * 64;
    const bf16* vaH = g_va_hi + (size_t)bh * MPAD * 64 + (size_t)a0 * 64;
    const bf16* vaL = g_va_lo + (size_t)bh * MPAD * 64 + (size_t)a0 * 64;

    auto load_tile = [&](int t, int s) {
        uint32_t st = sb + AQOF + s * ASTG;
#pragma unroll
        for (int it = 0; it < 2; ++it) {
            int idx = tid + it * 256;
            int row = idx >> 3, seg = (idx & 7) * 8;
            uint32_t so = row * 144 + seg * 2;
            size_t gk = (size_t)(t * 64 + row) * 64 + seg;
            cpasync16(st +         so, kaH + gk);
            cpasync16(st +  9216 + so, kaL + gk);
            cpasync16(st + 18432 + so, vaH + gk);
            cpasync16(st + 27648 + so, vaL + gk);
        }
    };

    float accO[8][4];
#pragma unroll
    for (int nt = 0; nt < 8; ++nt)
#pragma unroll
        for (int i = 0; i < 4; ++i) accO[nt][i] = 0.f;
    float lsum[2] = {0.f, 0.f};

    const int NT = AHALF / 64;  // 16
    load_tile(0, 0);
    CP_COMMIT();
    for (int t = 0; t < NT; ++t) {
        int s = t & 1;
        if (t + 1 < NT) { load_tile(t + 1, s ^ 1); CP_COMMIT(); CP_WAIT1(); }
        else CP_WAIT0();
        __syncthreads();
        uint32_t st = sb + AQOF + s * ASTG;

        // ---- QK ----
        float sc[8][4];
#pragma unroll
        for (int nt = 0; nt < 8; ++nt)
#pragma unroll
            for (int i = 0; i < 4; ++i) sc[nt][i] = 0.f;
#pragma unroll
        for (int ks = 0; ks < 4; ++ks) {
            uint32_t qh[4], ql[4];
            uint32_t qadr = sb + (wm + r16) * 144 + (ks * 16 + koff) * 2;
            ldsm4(qadr,         qh[0], qh[1], qh[2], qh[3]);
            ldsm4(qadr + 18432, ql[0], ql[1], ql[2], ql[3]);
#pragma unroll
            for (int ntp = 0; ntp < 4; ++ntp) {
                uint32_t kadr = st + (ntp * 16 + r16) * 144 + (ks * 16 + koff) * 2;
                uint32_t kh4[4], kl4[4];
                ldsm4(kadr,        kh4[0], kh4[1], kh4[2], kh4[3]);
                ldsm4(kadr + 9216, kl4[0], kl4[1], kl4[2], kl4[3]);
#pragma unroll
                for (int half = 0; half < 2; ++half) {
                    int nt = 2 * ntp + half;
                    uint32_t b0h = kh4[half], b1h = kh4[half + 2];
                    uint32_t b0l = kl4[half], b1l = kl4[half + 2];
                    MMA16(sc[nt], qh, b0h, b1h);
                    MMA16(sc[nt], qh, b0l, b1l);
                    MMA16(sc[nt], ql, b0h, b1h);
                }
            }
        }

        // ---- softmax ----
        bool need_mask = (a0 + t * 64 + 64) > MAREA;
        if (need_mask) {
#pragma unroll
            for (int nt = 0; nt < 8; ++nt) {
                int cb = a0 + t * 64 + nt * 8 + 2 * tig;
                float p0 = (cb     < MAREA) ? __expf(sc[nt][0]) : 0.f;
                float p1 = (cb + 1 < MAREA) ? __expf(sc[nt][1]) : 0.f;
                float p2 = (cb     < MAREA) ? __expf(sc[nt][2]) : 0.f;
                float p3 = (cb + 1 < MAREA) ? __expf(sc[nt][3]) : 0.f;
                sc[nt][0] = p0; sc[nt][1] = p1; sc[nt][2] = p2; sc[nt][3] = p3;
                lsum[0] += p0 + p1;
                lsum[1] += p2 + p3;
            }
        } else {
#pragma unroll
            for (int nt = 0; nt < 8; ++nt) {
                float p0 = __expf(sc[nt][0]);
                float p1 = __expf(sc[nt][1]);
                float p2 = __expf(sc[nt][2]);
                float p3 = __expf(sc[nt][3]);
                sc[nt][0] = p0; sc[nt][1] = p1; sc[nt][2] = p2; sc[nt][3] = p3;
                lsum[0] += p0 + p1;
                lsum[1] += p2 + p3;
            }
        }

        // ---- PV ----
#pragma unroll
        for (int kk = 0; kk < 4; ++kk) {
            uint32_t pah[4], pal[4];
            pah[0] = packhi2(sc[2 * kk][0],     sc[2 * kk][1]);
            pah[1] = packhi2(sc[2 * kk][2],     sc[2 * kk][3]);
            pah[2] = packhi2(sc[2 * kk + 1][0], sc[2 * kk + 1][1]);
            pah[3] = packhi2(sc[2 * kk + 1][2], sc[2 * kk + 1][3]);
            pal[0] = packlo2(sc[2 * kk][0],     sc[2 * kk][1],     pah[0]);
            pal[1] = packlo2(sc[2 * kk][2],     sc[2 * kk][3],     pah[1]);
            pal[2] = packlo2(sc[2 * kk + 1][0], sc[2 * kk + 1][1], pah[2]);
            pal[3] = packlo2(sc[2 * kk + 1][2], sc[2 * kk + 1][3], pah[3]);
#pragma unroll
            for (int ntp = 0; ntp < 4; ++ntp) {
                uint32_t vadr = st + 18432 + (kk * 16 + r16) * 144 + (ntp * 16 + koff) * 2;
                uint32_t vh4[4], vl4[4];
                ldsm4t(vadr,        vh4[0], vh4[1], vh4[2], vh4[3]);
                ldsm4t(vadr + 9216, vl4[0], vl4[1], vl4[2], vl4[3]);
#pragma unroll
                for (int half = 0; half < 2; ++half) {
                    int nt = 2 * ntp + half;
                    uint32_t b0h = vh4[half * 2], b1h = vh4[half * 2 + 1];
                    uint32_t b0l = vl4[half * 2], b1l = vl4[half * 2 + 1];
                    MMA16(accO[nt], pah, b0h, b1h);
                    MMA16(accO[nt], pah, b0l, b1l);
                    MMA16(accO[nt], pal, b0h, b1h);
                }
            }
        }
        __syncthreads();
    }

    // ---- write unnormalized partials ----
#pragma unroll
    for (int r = 0; r < 2; ++r) {
        lsum[r] += __shfl_xor_sync(0xFFFFFFFF, lsum[r], 1);
        lsum[r] += __shfl_xor_sync(0xFFFFFFFF, lsum[r], 2);
    }
    int row0 = b * N_ + q0 + wm + g;
    size_t obase = (size_t)z * ROWS_ * DIM_;
    size_t orow0 = obase + (size_t)row0 * DIM_ + h * 64;
    size_t orow1 = obase + (size_t)(row0 + 8) * DIM_ + h * 64;
#pragma unroll
    for (int nt = 0; nt < 8; ++nt) {
        int cc = nt * 8 + 2 * tig;
        *(float2*)(g_Opart + orow0 + cc) = make_float2(accO[nt][0], accO[nt][1]);
        *(float2*)(g_Opart + orow1 + cc) = make_float2(accO[nt][2], accO[nt][3]);
    }
    if (tig == 0) {
        g_lpart[z * ROWS_ * HEADS_ + row0 * HEADS_ + h]       = lsum[0];
        g_lpart[z * ROWS_ * HEADS_ + (row0 + 8) * HEADS_ + h] = lsum[1];
    }
}

// ---------------- combine: (O0+O1)/(l0+l1) -> attn hi/lo ------------------
__global__ __launch_bounds__(256)
void combine_kernel() {
    int i = blockIdx.x * 256 + threadIdx.x;
    int e = i * 2;
    int row = e / DIM_, col = e % DIM_;
    int h = col >> 6;
    float l = g_lpart[row * HEADS_ + h] + g_lpart[ROWS_ * HEADS_ + row * HEADS_ + h];
    float inv = 1.f / l;
    float2 a = *(float2*)(g_Opart + e);
    float2 bb = *(float2*)(g_Opart + (size_t)ROWS_ * DIM_ + e);
    float o0 = (a.x + bb.x) * inv, o1 = (a.y + bb.y) * inv;
    uint32_t h01 = packhi2(o0, o1);
    *(uint32_t*)(g_attn_hi + e) = h01;
    *(uint32_t*)(g_attn_lo + e) = packlo2(o0, o1, h01);
}

// ---------------- launch ---------------------------------------------------
extern "C" void kernel_launch(void* const* d_in, const int* in_sizes, int n_in,
                              void* d_out, int out_size) {
    const float* x     = (const float*)d_in[0];
    const float* w_qkv = (const float*)d_in[1];
    const float* w_q   = (const float*)d_in[2];
    const float* b_q   = (const float*)d_in[3];
    const float* w_k   = (const float*)d_in[4];
    const float* b_k   = (const float*)d_in[5];
    const float* w_v   = (const float*)d_in[6];
    const float* b_v   = (const float*)d_in[7];
    const float* w_o   = (const float*)d_in[8];
    const float* b_o   = (const float*)d_in[9];
    float* out = (float*)d_out;

    cudaFuncSetAttribute(gemm128_kernel, cudaFuncAttributeMaxDynamicSharedMemorySize, 2 * GSTG);
    cudaFuncSetAttribute(attn_kernel,    cudaFuncAttributeMaxDynamicSharedMemorySize, AQOF + 2 * ASTG);

    bf16 *x_hi, *x_lo, *wqkv_hi, *wqkv_lo, *wT_hi, *wT_lo, *woT_hi, *woT_lo;
    bf16 *weffT_hi, *weffT_lo, *qkvh_hi, *qkvh_lo, *attn_hi, *attn_lo;
    float *qkvh_f, *biasqkv;
    cudaGetSymbolAddress((void**)&x_hi, g_x_hi);       cudaGetSymbolAddress((void**)&x_lo, g_x_lo);
    cudaGetSymbolAddress((void**)&wqkv_hi, g_wqkv_hi); cudaGetSymbolAddress((void**)&wqkv_lo, g_wqkv_lo);
    cudaGetSymbolAddress((void**)&wT_hi, g_wT_hi);     cudaGetSymbolAddress((void**)&wT_lo, g_wT_lo);
    cudaGetSymbolAddress((void**)&woT_hi, g_woT_hi);   cudaGetSymbolAddress((void**)&woT_lo, g_woT_lo);
    cudaGetSymbolAddress((void**)&weffT_hi, g_weffT_hi); cudaGetSymbolAddress((void**)&weffT_lo, g_weffT_lo);
    cudaGetSymbolAddress((void**)&qkvh_f, g_qkvh_f);
    cudaGetSymbolAddress((void**)&qkvh_hi, g_qkvh_hi); cudaGetSymbolAddress((void**)&qkvh_lo, g_qkvh_lo);
    cudaGetSymbolAddress((void**)&attn_hi, g_attn_hi); cudaGetSymbolAddress((void**)&attn_lo, g_attn_lo);
    cudaGetSymbolAddress((void**)&biasqkv, g_biasqkv);

    // 1. fused prep
    prep_kernel<<<NB_CONVX4 + NB_CONVW4 + NB_CONVT + 9, 256>>>(
        x, w_qkv, w_q, w_k, w_v, w_o, b_q, b_k, b_v);

    // 2. compose W_eff^T
    {
        dim3 g(6, 6, 3);
        gemm128_kernel<<<g, 256, 2 * GSTG>>>(
            wT_hi, wT_lo, DIM_, wqkv_hi, wqkv_lo, K3,
            nullptr, weffT_hi, weffT_lo, DIM_, DIM_, nullptr,
            DIM_ * DIM_, DIM_, DIM_ * DIM_, 0);
    }

    // 3. qh|kh|vh = x @ W_eff + bias
    {
        dim3 g(K3 / 128, ROWS_ / 128, 1);
        gemm128_kernel<<<g, 256, 2 * GSTG>>>(x_hi, x_lo, DIM_, weffT_hi, weffT_lo, DIM_,
                                             qkvh_f, qkvh_hi, qkvh_lo, K3, DIM_, biasqkv,
                                             0, 0, 0, 1);
    }

    // 4. area pooling (R10 version; ncu-captured launch)
    {
        dim3 g(BH_, 4);
        pool_kernel<<<g, 256>>>();
    }

    // 5. attention (bh-major grid: same-bh CTAs co-resident for L2 reuse)
    {
        dim3 g(4, BH_);
        attn_kernel<<<g, 256, AQOF + 2 * ASTG>>>();
    }

    // 6. combine partials
    combine_kernel<<<ROWS_ * DIM_ / 512, 256>>>();

    // 7. out = attn @ w_o + b_o
    {
        dim3 g(DIM_ / 128, ROWS_ / 128, 1);
        gemm128_kernel<<<g, 256, 2 * GSTG>>>(attn_hi, attn_lo, DIM_, woT_hi, woT_lo, DIM_,
                                             out, nullptr, nullptr, DIM_, DIM_, b_o,
                                             0, 0, 0, 0);
    }
}

// round 15
// speedup vs baseline: 1.1691x; 1.1419x over previous
#include <cuda_runtime.h>
#include <cuda_bf16.h>
#include <cuda_fp16.h>
#include <cstdint>

#define B_     16
#define N_     256
#define DIM_   768
#define HEADS_ 12
#define DHEAD_ 64
#define BH_    192
#define MAREA  2025
#define MPAD   2048
#define ROWS_  4096
#define K3     2304

typedef __nv_bfloat16 bf16;

// ---------------- device global scratch ----------------
__device__ float g_biasqkv[K3];
__device__ bf16  g_x_hi[ROWS_*DIM_],   g_x_lo[ROWS_*DIM_];
__device__ bf16  g_wqkv_hi[DIM_*K3],   g_wqkv_lo[DIM_*K3];
__device__ bf16  g_wT_hi[3*DIM_*DIM_], g_wT_lo[3*DIM_*DIM_];
__device__ bf16  g_woT_hi[DIM_*DIM_],  g_woT_lo[DIM_*DIM_];
__device__ bf16  g_weffT_hi[K3*DIM_],  g_weffT_lo[K3*DIM_];
__device__ float g_qkvh_f[(size_t)ROWS_*K3];
__device__ bf16  g_qkvh_hi[(size_t)ROWS_*K3], g_qkvh_lo[(size_t)ROWS_*K3];
__device__ bf16  g_ka_hi[(size_t)BH_*MPAD*DHEAD_], g_ka_lo[(size_t)BH_*MPAD*DHEAD_];
__device__ __half g_va_h[(size_t)BH_*MPAD*DHEAD_];          // single fp16 V
__device__ bf16  g_attn_hi[(size_t)ROWS_*DIM_],    g_attn_lo[(size_t)ROWS_*DIM_];
__device__ float g_Opart[(size_t)2*ROWS_*DIM_];
__device__ float g_lpart[2*ROWS_*HEADS_];

// ---------------- helpers ----------------
__device__ __forceinline__ uint32_t smem_u32(const void* p) {
    uint32_t a;
    asm("{ .reg .u64 t; cvta.to.shared.u64 t, %1; cvt.u32.u64 %0, t; }" : "=r"(a) : "l"(p));
    return a;
}
__device__ __forceinline__ uint32_t packhi2(float x, float y) {
    __nv_bfloat162 t = __floats2bfloat162_rn(x, y);
    return *(uint32_t*)&t;
}
__device__ __forceinline__ uint32_t packlo2(float x, float y, uint32_t hp) {
    __nv_bfloat162 h = *(__nv_bfloat162*)&hp;
    __nv_bfloat162 t = __floats2bfloat162_rn(x - __bfloat162float(h.x),
                                             y - __bfloat162float(h.y));
    return *(uint32_t*)&t;
}
__device__ __forceinline__ uint32_t packh2(float x, float y) {
    __half2 t = __floats2half2_rn(x, y);
    return *(uint32_t*)&t;
}

#define MMA16(d, a, b0, b1) \
    asm volatile("mma.sync.aligned.m16n8k16.row.col.f32.bf16.bf16.f32 " \
        "{%0,%1,%2,%3}, {%4,%5,%6,%7}, {%8,%9}, {%0,%1,%2,%3};" \
        : "+f"((d)[0]), "+f"((d)[1]), "+f"((d)[2]), "+f"((d)[3]) \
        : "r"((a)[0]), "r"((a)[1]), "r"((a)[2]), "r"((a)[3]), "r"(b0), "r"(b1))

#define MMA16H(d, a, b0, b1) \
    asm volatile("mma.sync.aligned.m16n8k16.row.col.f32.f16.f16.f32 " \
        "{%0,%1,%2,%3}, {%4,%5,%6,%7}, {%8,%9}, {%0,%1,%2,%3};" \
        : "+f"((d)[0]), "+f"((d)[1]), "+f"((d)[2]), "+f"((d)[3]) \
        : "r"((a)[0]), "r"((a)[1]), "r"((a)[2]), "r"((a)[3]), "r"(b0), "r"(b1))

__device__ __forceinline__ void ldsm4(uint32_t addr, uint32_t& r0, uint32_t& r1,
                                      uint32_t& r2, uint32_t& r3) {
    asm volatile("ldmatrix.sync.aligned.m8n8.x4.shared.b16 {%0,%1,%2,%3}, [%4];"
                 : "=r"(r0), "=r"(r1), "=r"(r2), "=r"(r3) : "r"(addr));
}
__device__ __forceinline__ void ldsm4t(uint32_t addr, uint32_t& r0, uint32_t& r1,
                                       uint32_t& r2, uint32_t& r3) {
    asm volatile("ldmatrix.sync.aligned.m8n8.x4.trans.shared.b16 {%0,%1,%2,%3}, [%4];"
                 : "=r"(r0), "=r"(r1), "=r"(r2), "=r"(r3) : "r"(addr));
}
__device__ __forceinline__ void cpasync16(uint32_t saddr, const void* g) {
    asm volatile("cp.async.cg.shared.global [%0], [%1], 16;" :: "r"(saddr), "l"(g));
}
#define CP_COMMIT() asm volatile("cp.async.commit_group;" ::: "memory")
#define CP_WAIT0()  asm volatile("cp.async.wait_group 0;" ::: "memory")
#define CP_WAIT1()  asm volatile("cp.async.wait_group 1;" ::: "memory")

// ---------------- fused prep kernel (vectorized) ---------------------------
#define NB_CONVX4 3072
#define NB_CONVW4 1728
#define NB_CONVT  2304
__global__ __launch_bounds__(256)
void prep_kernel(const float* __restrict__ x, const float* __restrict__ w_qkv,
                 const float* __restrict__ w_q, const float* __restrict__ w_k,
                 const float* __restrict__ w_v, const float* __restrict__ w_o,
                 const float* __restrict__ bq, const float* __restrict__ bk,
                 const float* __restrict__ bv) {
    __shared__ float tile[32][33];
    int bx = blockIdx.x, t = threadIdx.x;
    if (bx < NB_CONVX4 + NB_CONVW4) {
        const float* src;
        bf16 *hi, *lo;
        int i;
        if (bx < NB_CONVX4) {
            i = (bx * 256 + t) * 4;
            src = x; hi = g_x_hi; lo = g_x_lo;
        } else {
            i = ((bx - NB_CONVX4) * 256 + t) * 4;
            src = w_qkv; hi = g_wqkv_hi; lo = g_wqkv_lo;
        }
        float4 v = *(const float4*)(src + i);
        uint32_t h01 = packhi2(v.x, v.y), h23 = packhi2(v.z, v.w);
        uint32_t l01 = packlo2(v.x, v.y, h01), l23 = packlo2(v.z, v.w, h23);
        *(uint2*)(hi + i) = make_uint2(h01, h23);
        *(uint2*)(lo + i) = make_uint2(l01, l23);
    } else if (bx < NB_CONVX4 + NB_CONVW4 + NB_CONVT) {
        int id = bx - (NB_CONVX4 + NB_CONVW4);
        int seg = id / 576, rem = id % 576;
        int c0 = (rem % 24) * 32, r0 = (rem / 24) * 32;
        const float* src = (seg == 0) ? w_q : (seg == 1) ? w_k : (seg == 2) ? w_v : w_o;
        bf16* hi = (seg < 3) ? (g_wT_hi + (size_t)seg * DIM_ * DIM_) : g_woT_hi;
        bf16* lo = (seg < 3) ? (g_wT_lo + (size_t)seg * DIM_ * DIM_) : g_woT_lo;
        int tx = t & 31, ty = t >> 5;
#pragma unroll
        for (int i = 0; i < 4; ++i)
            tile[ty + i * 8][tx] = src[(size_t)(r0 + ty + i * 8) * DIM_ + c0 + tx];
        __syncthreads();
#pragma unroll
        for (int i = 0; i < 4; ++i) {
            float v = tile[tx][ty + i * 8];
            size_t o = (size_t)(c0 + ty + i * 8) * DIM_ + r0 + tx;
            bf16 h = __float2bfloat16(v);
            hi[o] = h;
            lo[o] = __float2bfloat16(v - __bfloat162float(h));
        }
    } else {
        int idx = (bx - (NB_CONVX4 + NB_CONVW4 + NB_CONVT)) * 256 + t;
        int seg = idx / 768;
        const float* s = (seg == 0) ? bq : (seg == 1) ? bk : bv;
        g_biasqkv[idx] = s[idx % 768];
    }
}

// ---------------- 128x128 warp-MMA GEMM, BK=32, 2 CTAs/SM -----------------
#define GSTG 40960
__global__ __launch_bounds__(256, 2)
void gemm128_kernel(const bf16* __restrict__ Ah, const bf16* __restrict__ Al, int lda,
                    const bf16* __restrict__ Bh, const bf16* __restrict__ Bl, int ldb,
                    float* __restrict__ Cf, bf16* __restrict__ Chi, bf16* __restrict__ Clo,
                    int ldc, int K, const float* __restrict__ bias,
                    int sAz, int sBz, int sCz, int qkvMode) {
    extern __shared__ char smem[];
    uint32_t sb = smem_u32(smem);
    int z = blockIdx.z;
    Ah += (size_t)z * sAz; Al += (size_t)z * sAz;
    Bh += (size_t)z * sBz; Bl += (size_t)z * sBz;
    if (Cf)  Cf  += (size_t)z * sCz;
    if (Chi) { Chi += (size_t)z * sCz; Clo += (size_t)z * sCz; }

    int tid = threadIdx.x, lane = tid & 31, wid = tid >> 5;
    int g = lane >> 2, tig = lane & 3;
    int wm = (wid >> 1) * 32, wn = (wid & 1) * 64;
    int m0 = blockIdx.y * 128, n0 = blockIdx.x * 128;
    int r16 = lane & 15, koff = (lane >> 4) * 8;

    bool doF = Cf  && (qkvMode == 0 || n0 >= 768);
    bool doH = Chi && (qkvMode == 0 || n0 < 768);

    float acc[2][8][4];
#pragma unroll
    for (int mt = 0; mt < 2; ++mt)
#pragma unroll
        for (int nt = 0; nt < 8; ++nt)
#pragma unroll
            for (int i = 0; i < 4; ++i) acc[mt][nt][i] = 0.f;

    auto load_chunk = [&](int kc, int s) {
        uint32_t st = sb + s * GSTG;
#pragma unroll
        for (int it = 0; it < 2; ++it) {
            int idx = tid + it * 256;
            int row = idx >> 2, seg8 = (idx & 3) * 8;
            uint32_t so = row * 80 + seg8 * 2;
            size_t ga = (size_t)(m0 + row) * lda + kc + seg8;
            size_t gb = (size_t)(n0 + row) * ldb + kc + seg8;
            cpasync16(st +         so, Ah + ga);
            cpasync16(st + 10240 + so, Al + ga);
            cpasync16(st + 20480 + so, Bh + gb);
            cpasync16(st + 30720 + so, Bl + gb);
        }
    };

    int nch = K / 32;
    load_chunk(0, 0);
    CP_COMMIT();
    for (int c = 0; c < nch; ++c) {
        int s = c & 1;
        if (c + 1 < nch) { load_chunk((c + 1) * 32, s ^ 1); CP_COMMIT(); CP_WAIT1(); }
        else CP_WAIT0();
        __syncthreads();
        uint32_t st = sb + s * GSTG;
#pragma unroll
        for (int ks = 0; ks < 2; ++ks) {
            uint32_t ah[2][4], al[2][4];
#pragma unroll
            for (int mt = 0; mt < 2; ++mt) {
                uint32_t aadr = st + (wm + mt * 16 + r16) * 80 + (ks * 16 + koff) * 2;
                ldsm4(aadr,         ah[mt][0], ah[mt][1], ah[mt][2], ah[mt][3]);
                ldsm4(aadr + 10240, al[mt][0], al[mt][1], al[mt][2], al[mt][3]);
            }
#pragma unroll
            for (int ntp = 0; ntp < 4; ++ntp) {
                uint32_t badr = st + 20480 + (wn + ntp * 16 + r16) * 80 + (ks * 16 + koff) * 2;
                uint32_t bh4[4], bl4[4];
                ldsm4(badr,         bh4[0], bh4[1], bh4[2], bh4[3]);
                ldsm4(badr + 10240, bl4[0], bl4[1], bl4[2], bl4[3]);
#pragma unroll
                for (int half = 0; half < 2; ++half) {
                    int nt = 2 * ntp + half;
                    uint32_t bh0 = bh4[half], bh1 = bh4[half + 2];
                    uint32_t bl0 = bl4[half], bl1 = bl4[half + 2];
#pragma unroll
                    for (int mt = 0; mt < 2; ++mt) {
                        MMA16(acc[mt][nt], ah[mt], bh0, bh1);
                        MMA16(acc[mt][nt], ah[mt], bl0, bl1);
                        MMA16(acc[mt][nt], al[mt], bh0, bh1);
                    }
                }
            }
        }
        __syncthreads();
    }
#pragma unroll
    for (int mt = 0; mt < 2; ++mt)
#pragma unroll
        for (int nt = 0; nt < 8; ++nt) {
            int row = m0 + wm + mt * 16 + g;
            int col = n0 + wn + nt * 8 + 2 * tig;
            float v0 = acc[mt][nt][0], v1 = acc[mt][nt][1];
            float v2 = acc[mt][nt][2], v3 = acc[mt][nt][3];
            if (bias) {
                float b0v = bias[col], b1v = bias[col + 1];
                v0 += b0v; v1 += b1v; v2 += b0v; v3 += b1v;
            }
            if (doF) {
                *(float2*)(Cf + (size_t)row * ldc + col)       = make_float2(v0, v1);
                *(float2*)(Cf + (size_t)(row + 8) * ldc + col) = make_float2(v2, v3);
            }
            if (doH) {
                uint32_t h01 = packhi2(v0, v1), h23 = packhi2(v2, v3);
                *(uint32_t*)(Chi + (size_t)row * ldc + col)       = h01;
                *(uint32_t*)(Chi + (size_t)(row + 8) * ldc + col) = h23;
                *(uint32_t*)(Clo + (size_t)row * ldc + col)       = packlo2(v0, v1, h01);
                *(uint32_t*)(Clo + (size_t)(row + 8) * ldc + col) = packlo2(v2, v3, h23);
            }
        }
}

// ---------------- area pooling: K hi/lo + V single fp16 -------------------
__global__ __launch_bounds__(256)
void pool_kernel() {
    int bh = blockIdx.x, cbase = blockIdx.y * 16;
    int b = bh / HEADS_, h = bh % HEADS_;
    __shared__ float sat[16][289];
    int t = threadIdx.x;
    const int cnts[9] = {256, 240, 224, 240, 225, 210, 224, 210, 196};

    for (int pass = 0; pass < 2; ++pass) {
        const float* base = g_qkvh_f + (size_t)(b * N_) * K3 + (pass ? 2 * DIM_ : DIM_)
                          + h * DHEAD_ + cbase;
        {
            int ch = t & 15, row = t >> 4;
            if (row == 0)
#pragma unroll
                for (int x = 0; x < 17; ++x) sat[ch][x] = 0.f;
            sat[ch][(row + 1) * 17] = 0.f;
            float vals[16];
#pragma unroll
            for (int x = 0; x < 16; ++x)
                vals[x] = base[(size_t)(row * 16 + x) * K3 + ch];
            float acc = 0.f;
#pragma unroll
            for (int x = 0; x < 16; ++x) {
                acc += vals[x];
                sat[ch][(row + 1) * 17 + x + 1] = acc;
            }
        }
        __syncthreads();
        {
            int ch = t >> 4, col = (t & 15) + 1;
            float acc = 0.f;
#pragma unroll
            for (int y = 1; y <= 16; ++y) {
                acc += sat[ch][y * 17 + col];
                sat[ch][y * 17 + col] = acc;
            }
        }
        __syncthreads();
        int sub = t & 1;
        for (int m = t >> 1; m < MPAD; m += 128) {
            float scale = 0.f;
            int y0 = 0, x0 = 0, ah = 1, aw = 1;
            bool valid = (m < MAREA);
            if (valid) {
                int rem = m, seg = 0;
                while (rem >= cnts[seg]) { rem -= cnts[seg]; ++seg; }
                ah = seg / 3 + 1; aw = seg % 3 + 1;
                int w = 17 - aw;
                y0 = rem / w; x0 = rem % w;
                scale = (pass == 0) ? 1.f / (float)(ah * aw) : 1.f;
            }
            int iA = (y0 + ah) * 17 + x0 + aw, iB = y0 * 17 + x0 + aw;
            int iC = (y0 + ah) * 17 + x0,      iD = y0 * 17 + x0;
            size_t o = ((size_t)bh * MPAD + m) * DHEAD_ + cbase + sub * 8;
            if (pass == 0) {
                bf16 hv[8], lv[8];
#pragma unroll
                for (int c = 0; c < 8; ++c) {
                    int ch = sub * 8 + c;
                    float s = 0.f;
                    if (valid)
                        s = (sat[ch][iA] - sat[ch][iB] - sat[ch][iC] + sat[ch][iD]) * scale;
                    hv[c] = __float2bfloat16(s);
                    lv[c] = __float2bfloat16(s - __bfloat162float(hv[c]));
                }
                *(uint4*)(g_ka_hi + o) = *(uint4*)hv;
                *(uint4*)(g_ka_lo + o) = *(uint4*)lv;
            } else {
                __half vv[8];
#pragma unroll
                for (int c = 0; c < 8; ++c) {
                    int ch = sub * 8 + c;
                    float s = 0.f;
                    if (valid)
                        s = (sat[ch][iA] - sat[ch][iB] - sat[ch][iC] + sat[ch][iD]) * scale;
                    vv[c] = __float2half(s);
                }
                *(uint4*)(g_va_h + o) = *(uint4*)vv;
            }
        }
        __syncthreads();
    }
}

// ---------------- attention: QK 3-term bf16, PV single fp16 ---------------
// Stage: Kh 0, Kl 9216, V 18432 (64 rows x 144B each); ASTG 27648.
#define ASTG 27648
#define AQOF 36864
#define AHALF (MPAD / 2)
__global__ __launch_bounds__(256, 2)
void attn_kernel() {
    extern __shared__ char smem[];
    uint32_t sb = smem_u32(smem);
    int tid = threadIdx.x, lane = tid & 31, wid = tid >> 5;
    int g = lane >> 2, tig = lane & 3;
    int wm = wid * 16;
    int bh = blockIdx.y;
    int q0 = (blockIdx.x >> 1) * 128;
    int z = blockIdx.x & 1;
    int a0 = z * AHALF;
    int b = bh / HEADS_, h = bh % HEADS_;
    int r16 = lane & 15, koff = (lane >> 4) * 8;

    bf16* Qs = (bf16*)smem;
#pragma unroll
    for (int it = 0; it < 4; ++it) {
        int idx = tid + it * 256;
        int row = idx >> 3, seg = (idx & 7) * 8;
        size_t src = (size_t)(b * N_ + q0 + row) * K3 + h * 64 + seg;
        *(uint4*)(Qs + row * 72 + seg)        = *(const uint4*)(g_qkvh_hi + src);
        *(uint4*)(Qs + 9216 + row * 72 + seg) = *(const uint4*)(g_qkvh_lo + src);
    }

    const bf16* kaH = g_ka_hi + (size_t)bh * MPAD * 64 + (size_t)a0 * 64;
    const bf16* kaL = g_ka_lo + (size_t)bh * MPAD * 64 + (size_t)a0 * 64;
    const __half* vaF = g_va_h + (size_t)bh * MPAD * 64 + (size_t)a0 * 64;

    auto load_tile = [&](int t, int s) {
        uint32_t st = sb + AQOF + s * ASTG;
#pragma unroll
        for (int it = 0; it < 2; ++it) {
            int idx = tid + it * 256;
            int row = idx >> 3, seg = (idx & 7) * 8;
            uint32_t so = row * 144 + seg * 2;
            size_t gk = (size_t)(t * 64 + row) * 64 + seg;
            cpasync16(st +         so, kaH + gk);
            cpasync16(st +  9216 + so, kaL + gk);
            cpasync16(st + 18432 + so, vaF + gk);
        }
    };

    float accO[8][4];
#pragma unroll
    for (int nt = 0; nt < 8; ++nt)
#pragma unroll
        for (int i = 0; i < 4; ++i) accO[nt][i] = 0.f;
    float lsum[2] = {0.f, 0.f};

    const int NT = AHALF / 64;  // 16
    load_tile(0, 0);
    CP_COMMIT();
    for (int t = 0; t < NT; ++t) {
        int s = t & 1;
        if (t + 1 < NT) { load_tile(t + 1, s ^ 1); CP_COMMIT(); CP_WAIT1(); }
        else CP_WAIT0();
        __syncthreads();
        uint32_t st = sb + AQOF + s * ASTG;

        // ---- QK (3-term bf16) ----
        float sc[8][4];
#pragma unroll
        for (int nt = 0; nt < 8; ++nt)
#pragma unroll
            for (int i = 0; i < 4; ++i) sc[nt][i] = 0.f;
#pragma unroll
        for (int ks = 0; ks < 4; ++ks) {
            uint32_t qh[4], ql[4];
            uint32_t qadr = sb + (wm + r16) * 144 + (ks * 16 + koff) * 2;
            ldsm4(qadr,         qh[0], qh[1], qh[2], qh[3]);
            ldsm4(qadr + 18432, ql[0], ql[1], ql[2], ql[3]);
#pragma unroll
            for (int ntp = 0; ntp < 4; ++ntp) {
                uint32_t kadr = st + (ntp * 16 + r16) * 144 + (ks * 16 + koff) * 2;
                uint32_t kh4[4], kl4[4];
                ldsm4(kadr,        kh4[0], kh4[1], kh4[2], kh4[3]);
                ldsm4(kadr + 9216, kl4[0], kl4[1], kl4[2], kl4[3]);
#pragma unroll
                for (int half = 0; half < 2; ++half) {
                    int nt = 2 * ntp + half;
                    uint32_t b0h = kh4[half], b1h = kh4[half + 2];
                    uint32_t b0l = kl4[half], b1l = kl4[half + 2];
                    MMA16(sc[nt], qh, b0h, b1h);
                    MMA16(sc[nt], qh, b0l, b1l);
                    MMA16(sc[nt], ql, b0h, b1h);
                }
            }
        }

        // ---- softmax ----
        bool need_mask = (a0 + t * 64 + 64) > MAREA;
        if (need_mask) {
#pragma unroll
            for (int nt = 0; nt < 8; ++nt) {
                int cb = a0 + t * 64 + nt * 8 + 2 * tig;
                float p0 = (cb     < MAREA) ? __expf(sc[nt][0]) : 0.f;
                float p1 = (cb + 1 < MAREA) ? __expf(sc[nt][1]) : 0.f;
                float p2 = (cb     < MAREA) ? __expf(sc[nt][2]) : 0.f;
                float p3 = (cb + 1 < MAREA) ? __expf(sc[nt][3]) : 0.f;
                sc[nt][0] = p0; sc[nt][1] = p1; sc[nt][2] = p2; sc[nt][3] = p3;
                lsum[0] += p0 + p1;
                lsum[1] += p2 + p3;
            }
        } else {
#pragma unroll
            for (int nt = 0; nt < 8; ++nt) {
                float p0 = __expf(sc[nt][0]);
                float p1 = __expf(sc[nt][1]);
                float p2 = __expf(sc[nt][2]);
                float p3 = __expf(sc[nt][3]);
                sc[nt][0] = p0; sc[nt][1] = p1; sc[nt][2] = p2; sc[nt][3] = p3;
                lsum[0] += p0 + p1;
                lsum[1] += p2 + p3;
            }
        }

        // ---- PV (single fp16 MMA) ----
#pragma unroll
        for (int kk = 0; kk < 4; ++kk) {
            uint32_t pa[4];
            pa[0] = packh2(sc[2 * kk][0],     sc[2 * kk][1]);
            pa[1] = packh2(sc[2 * kk][2],     sc[2 * kk][3]);
            pa[2] = packh2(sc[2 * kk + 1][0], sc[2 * kk + 1][1]);
            pa[3] = packh2(sc[2 * kk + 1][2], sc[2 * kk + 1][3]);
#pragma unroll
            for (int ntp = 0; ntp < 4; ++ntp) {
                uint32_t vadr = st + 18432 + (kk * 16 + r16) * 144 + (ntp * 16 + koff) * 2;
                uint32_t vh4[4];
                ldsm4t(vadr, vh4[0], vh4[1], vh4[2], vh4[3]);
#pragma unroll
                for (int half = 0; half < 2; ++half) {
                    int nt = 2 * ntp + half;
                    MMA16H(accO[nt], pa, vh4[half * 2], vh4[half * 2 + 1]);
                }
            }
        }
        __syncthreads();
    }

    // ---- write unnormalized partials ----
#pragma unroll
    for (int r = 0; r < 2; ++r) {
        lsum[r] += __shfl_xor_sync(0xFFFFFFFF, lsum[r], 1);
        lsum[r] += __shfl_xor_sync(0xFFFFFFFF, lsum[r], 2);
    }
    int row0 = b * N_ + q0 + wm + g;
    size_t obase = (size_t)z * ROWS_ * DIM_;
    size_t orow0 = obase + (size_t)row0 * DIM_ + h * 64;
    size_t orow1 = obase + (size_t)(row0 + 8) * DIM_ + h * 64;
#pragma unroll
    for (int nt = 0; nt < 8; ++nt) {
        int cc = nt * 8 + 2 * tig;
        *(float2*)(g_Opart + orow0 + cc) = make_float2(accO[nt][0], accO[nt][1]);
        *(float2*)(g_Opart + orow1 + cc) = make_float2(accO[nt][2], accO[nt][3]);
    }
    if (tig == 0) {
        g_lpart[z * ROWS_ * HEADS_ + row0 * HEADS_ + h]       = lsum[0];
        g_lpart[z * ROWS_ * HEADS_ + (row0 + 8) * HEADS_ + h] = lsum[1];
    }
}

// ---------------- combine: (O0+O1)/(l0+l1) -> attn hi/lo ------------------
__global__ __launch_bounds__(256)
void combine_kernel() {
    int i = blockIdx.x * 256 + threadIdx.x;
    int e = i * 2;
    int row = e / DIM_, col = e % DIM_;
    int h = col >> 6;
    float l = g_lpart[row * HEADS_ + h] + g_lpart[ROWS_ * HEADS_ + row * HEADS_ + h];
    float inv = 1.f / l;
    float2 a = *(float2*)(g_Opart + e);
    float2 bb = *(float2*)(g_Opart + (size_t)ROWS_ * DIM_ + e);
    float o0 = (a.x + bb.x) * inv, o1 = (a.y + bb.y) * inv;
    uint32_t h01 = packhi2(o0, o1);
    *(uint32_t*)(g_attn_hi + e) = h01;
    *(uint32_t*)(g_attn_lo + e) = packlo2(o0, o1, h01);
}

// ---------------- launch ---------------------------------------------------
extern "C" void kernel_launch(void* const* d_in, const int* in_sizes, int n_in,
                              void* d_out, int out_size) {
    const float* x     = (const float*)d_in[0];
    const float* w_qkv = (const float*)d_in[1];
    const float* w_q   = (const float*)d_in[2];
    const float* b_q   = (const float*)d_in[3];
    const float* w_k   = (const float*)d_in[4];
    const float* b_k   = (const float*)d_in[5];
    const float* w_v   = (const float*)d_in[6];
    const float* b_v   = (const float*)d_in[7];
    const float* w_o   = (const float*)d_in[8];
    const float* b_o   = (const float*)d_in[9];
    float* out = (float*)d_out;

    cudaFuncSetAttribute(gemm128_kernel, cudaFuncAttributeMaxDynamicSharedMemorySize, 2 * GSTG);
    cudaFuncSetAttribute(attn_kernel,    cudaFuncAttributeMaxDynamicSharedMemorySize, AQOF + 2 * ASTG);

    bf16 *x_hi, *x_lo, *wqkv_hi, *wqkv_lo, *wT_hi, *wT_lo, *woT_hi, *woT_lo;
    bf16 *weffT_hi, *weffT_lo, *qkvh_hi, *qkvh_lo, *attn_hi, *attn_lo;
    float *qkvh_f, *biasqkv;
    cudaGetSymbolAddress((void**)&x_hi, g_x_hi);       cudaGetSymbolAddress((void**)&x_lo, g_x_lo);
    cudaGetSymbolAddress((void**)&wqkv_hi, g_wqkv_hi); cudaGetSymbolAddress((void**)&wqkv_lo, g_wqkv_lo);
    cudaGetSymbolAddress((void**)&wT_hi, g_wT_hi);     cudaGetSymbolAddress((void**)&wT_lo, g_wT_lo);
    cudaGetSymbolAddress((void**)&woT_hi, g_woT_hi);   cudaGetSymbolAddress((void**)&woT_lo, g_woT_lo);
    cudaGetSymbolAddress((void**)&weffT_hi, g_weffT_hi); cudaGetSymbolAddress((void**)&weffT_lo, g_weffT_lo);
    cudaGetSymbolAddress((void**)&qkvh_f, g_qkvh_f);
    cudaGetSymbolAddress((void**)&qkvh_hi, g_qkvh_hi); cudaGetSymbolAddress((void**)&qkvh_lo, g_qkvh_lo);
    cudaGetSymbolAddress((void**)&attn_hi, g_attn_hi); cudaGetSymbolAddress((void**)&attn_lo, g_attn_lo);
    cudaGetSymbolAddress((void**)&biasqkv, g_biasqkv);

    // 1. fused prep
    prep_kernel<<<NB_CONVX4 + NB_CONVW4 + NB_CONVT + 9, 256>>>(
        x, w_qkv, w_q, w_k, w_v, w_o, b_q, b_k, b_v);

    // 2. compose W_eff^T
    {
        dim3 g(6, 6, 3);
        gemm128_kernel<<<g, 256, 2 * GSTG>>>(
            wT_hi, wT_lo, DIM_, wqkv_hi, wqkv_lo, K3,
            nullptr, weffT_hi, weffT_lo, DIM_, DIM_, nullptr,
            DIM_ * DIM_, DIM_, DIM_ * DIM_, 0);
    }

    // 3. qh|kh|vh = x @ W_eff + bias
    {
        dim3 g(K3 / 128, ROWS_ / 128, 1);
        gemm128_kernel<<<g, 256, 2 * GSTG>>>(x_hi, x_lo, DIM_, weffT_hi, weffT_lo, DIM_,
                                             qkvh_f, qkvh_hi, qkvh_lo, K3, DIM_, biasqkv,
                                             0, 0, 0, 1);
    }

    // 4. area pooling
    {
        dim3 g(BH_, 4);
        pool_kernel<<<g, 256>>>();
    }

    // 5. attention (bh-major grid)
    {
        dim3 g(4, BH_);
        attn_kernel<<<g, 256, AQOF + 2 * ASTG>>>();
    }

    // 6. combine partials
    combine_kernel<<<ROWS_ * DIM_ / 512, 256>>>();

    // 7. out = attn @ w_o + b_o
    {
        dim3 g(DIM_ / 128, ROWS_ / 128, 1);
        gemm128_kernel<<<g, 256, 2 * GSTG>>>(attn_hi, attn_lo, DIM_, woT_hi, woT_lo, DIM_,
                                             out, nullptr, nullptr, DIM_, DIM_, b_o,
                                             0, 0, 0, 0);
    }
}

// round 16
// speedup vs baseline: 1.2795x; 1.0944x over previous
#include <cuda_runtime.h>
#include <cuda_bf16.h>
#include <cuda_fp16.h>
#include <cstdint>

#define B_     16
#define N_     256
#define DIM_   768
#define HEADS_ 12
#define DHEAD_ 64
#define BH_    192
#define MAREA  2025
#define MPAD   2048
#define ROWS_  4096
#define K3     2304

typedef __nv_bfloat16 bf16;

// ---------------- device global scratch ----------------
__device__ float g_biasqkv[K3];
__device__ bf16  g_x_hi[ROWS_*DIM_],   g_x_lo[ROWS_*DIM_];
__device__ bf16  g_wqkv_hi[DIM_*K3],   g_wqkv_lo[DIM_*K3];
__device__ bf16  g_wT_hi[3*DIM_*DIM_], g_wT_lo[3*DIM_*DIM_];
__device__ bf16  g_woT_hi[DIM_*DIM_],  g_woT_lo[DIM_*DIM_];
__device__ bf16  g_weffT_hi[K3*DIM_],  g_weffT_lo[K3*DIM_];
__device__ float g_qkvh_f[(size_t)ROWS_*K3];
// q columns hold fp16 hi/lo bits; k/v columns unused in these arrays
__device__ bf16  g_qkvh_hi[(size_t)ROWS_*K3], g_qkvh_lo[(size_t)ROWS_*K3];
__device__ __half g_ka_h[(size_t)BH_*MPAD*DHEAD_];   // K area means, single fp16
__device__ __half g_va_h[(size_t)BH_*MPAD*DHEAD_];   // V area sums, single fp16
__device__ bf16  g_attn_hi[(size_t)ROWS_*DIM_],    g_attn_lo[(size_t)ROWS_*DIM_];
__device__ float g_Opart[(size_t)2*ROWS_*DIM_];
__device__ float g_lpart[2*ROWS_*HEADS_];

// ---------------- helpers ----------------
__device__ __forceinline__ uint32_t smem_u32(const void* p) {
    uint32_t a;
    asm("{ .reg .u64 t; cvta.to.shared.u64 t, %1; cvt.u32.u64 %0, t; }" : "=r"(a) : "l"(p));
    return a;
}
__device__ __forceinline__ uint32_t packhi2(float x, float y) {
    __nv_bfloat162 t = __floats2bfloat162_rn(x, y);
    return *(uint32_t*)&t;
}
__device__ __forceinline__ uint32_t packlo2(float x, float y, uint32_t hp) {
    __nv_bfloat162 h = *(__nv_bfloat162*)&hp;
    __nv_bfloat162 t = __floats2bfloat162_rn(x - __bfloat162float(h.x),
                                             y - __bfloat162float(h.y));
    return *(uint32_t*)&t;
}
__device__ __forceinline__ uint32_t packh2(float x, float y) {
    __half2 t = __floats2half2_rn(x, y);
    return *(uint32_t*)&t;
}
__device__ __forceinline__ uint32_t packh2lo(float x, float y, uint32_t hp) {
    __half2 h = *(__half2*)&hp;
    __half2 t = __floats2half2_rn(x - __half2float(h.x), y - __half2float(h.y));
    return *(uint32_t*)&t;
}

#define MMA16(d, a, b0, b1) \
    asm volatile("mma.sync.aligned.m16n8k16.row.col.f32.bf16.bf16.f32 " \
        "{%0,%1,%2,%3}, {%4,%5,%6,%7}, {%8,%9}, {%0,%1,%2,%3};" \
        : "+f"((d)[0]), "+f"((d)[1]), "+f"((d)[2]), "+f"((d)[3]) \
        : "r"((a)[0]), "r"((a)[1]), "r"((a)[2]), "r"((a)[3]), "r"(b0), "r"(b1))

#define MMA16H(d, a, b0, b1) \
    asm volatile("mma.sync.aligned.m16n8k16.row.col.f32.f16.f16.f32 " \
        "{%0,%1,%2,%3}, {%4,%5,%6,%7}, {%8,%9}, {%0,%1,%2,%3};" \
        : "+f"((d)[0]), "+f"((d)[1]), "+f"((d)[2]), "+f"((d)[3]) \
        : "r"((a)[0]), "r"((a)[1]), "r"((a)[2]), "r"((a)[3]), "r"(b0), "r"(b1))

__device__ __forceinline__ void ldsm4(uint32_t addr, uint32_t& r0, uint32_t& r1,
                                      uint32_t& r2, uint32_t& r3) {
    asm volatile("ldmatrix.sync.aligned.m8n8.x4.shared.b16 {%0,%1,%2,%3}, [%4];"
                 : "=r"(r0), "=r"(r1), "=r"(r2), "=r"(r3) : "r"(addr));
}
__device__ __forceinline__ void ldsm4t(uint32_t addr, uint32_t& r0, uint32_t& r1,
                                       uint32_t& r2, uint32_t& r3) {
    asm volatile("ldmatrix.sync.aligned.m8n8.x4.trans.shared.b16 {%0,%1,%2,%3}, [%4];"
                 : "=r"(r0), "=r"(r1), "=r"(r2), "=r"(r3) : "r"(addr));
}
__device__ __forceinline__ void cpasync16(uint32_t saddr, const void* g) {
    asm volatile("cp.async.cg.shared.global [%0], [%1], 16;" :: "r"(saddr), "l"(g));
}
#define CP_COMMIT() asm volatile("cp.async.commit_group;" ::: "memory")
#define CP_WAIT0()  asm volatile("cp.async.wait_group 0;" ::: "memory")
#define CP_WAIT1()  asm volatile("cp.async.wait_group 1;" ::: "memory")

// ---------------- fused prep kernel (vectorized) ---------------------------
#define NB_CONVX4 3072
#define NB_CONVW4 1728
#define NB_CONVT  2304
__global__ __launch_bounds__(256)
void prep_kernel(const float* __restrict__ x, const float* __restrict__ w_qkv,
                 const float* __restrict__ w_q, const float* __restrict__ w_k,
                 const float* __restrict__ w_v, const float* __restrict__ w_o,
                 const float* __restrict__ bq, const float* __restrict__ bk,
                 const float* __restrict__ bv) {
    __shared__ float tile[32][33];
    int bx = blockIdx.x, t = threadIdx.x;
    if (bx < NB_CONVX4 + NB_CONVW4) {
        const float* src;
        bf16 *hi, *lo;
        int i;
        if (bx < NB_CONVX4) {
            i = (bx * 256 + t) * 4;
            src = x; hi = g_x_hi; lo = g_x_lo;
        } else {
            i = ((bx - NB_CONVX4) * 256 + t) * 4;
            src = w_qkv; hi = g_wqkv_hi; lo = g_wqkv_lo;
        }
        float4 v = *(const float4*)(src + i);
        uint32_t h01 = packhi2(v.x, v.y), h23 = packhi2(v.z, v.w);
        uint32_t l01 = packlo2(v.x, v.y, h01), l23 = packlo2(v.z, v.w, h23);
        *(uint2*)(hi + i) = make_uint2(h01, h23);
        *(uint2*)(lo + i) = make_uint2(l01, l23);
    } else if (bx < NB_CONVX4 + NB_CONVW4 + NB_CONVT) {
        int id = bx - (NB_CONVX4 + NB_CONVW4);
        int seg = id / 576, rem = id % 576;
        int c0 = (rem % 24) * 32, r0 = (rem / 24) * 32;
        const float* src = (seg == 0) ? w_q : (seg == 1) ? w_k : (seg == 2) ? w_v : w_o;
        bf16* hi = (seg < 3) ? (g_wT_hi + (size_t)seg * DIM_ * DIM_) : g_woT_hi;
        bf16* lo = (seg < 3) ? (g_wT_lo + (size_t)seg * DIM_ * DIM_) : g_woT_lo;
        int tx = t & 31, ty = t >> 5;
#pragma unroll
        for (int i = 0; i < 4; ++i)
            tile[ty + i * 8][tx] = src[(size_t)(r0 + ty + i * 8) * DIM_ + c0 + tx];
        __syncthreads();
#pragma unroll
        for (int i = 0; i < 4; ++i) {
            float v = tile[tx][ty + i * 8];
            size_t o = (size_t)(c0 + ty + i * 8) * DIM_ + r0 + tx;
            bf16 h = __float2bfloat16(v);
            hi[o] = h;
            lo[o] = __float2bfloat16(v - __bfloat162float(h));
        }
    } else {
        int idx = (bx - (NB_CONVX4 + NB_CONVW4 + NB_CONVT)) * 256 + t;
        int seg = idx / 768;
        const float* s = (seg == 0) ? bq : (seg == 1) ? bk : bv;
        g_biasqkv[idx] = s[idx % 768];
    }
}

// ---------------- 128x128 warp-MMA GEMM, BK=32, 2 CTAs/SM -----------------
// qkvMode==1: f32 only for n0>=768 (k/v cols), hi/lo (fp16 format) for q cols.
#define GSTG 40960
__global__ __launch_bounds__(256, 2)
void gemm128_kernel(const bf16* __restrict__ Ah, const bf16* __restrict__ Al, int lda,
                    const bf16* __restrict__ Bh, const bf16* __restrict__ Bl, int ldb,
                    float* __restrict__ Cf, bf16* __restrict__ Chi, bf16* __restrict__ Clo,
                    int ldc, int K, const float* __restrict__ bias,
                    int sAz, int sBz, int sCz, int qkvMode) {
    extern __shared__ char smem[];
    uint32_t sb = smem_u32(smem);
    int z = blockIdx.z;
    Ah += (size_t)z * sAz; Al += (size_t)z * sAz;
    Bh += (size_t)z * sBz; Bl += (size_t)z * sBz;
    if (Cf)  Cf  += (size_t)z * sCz;
    if (Chi) { Chi += (size_t)z * sCz; Clo += (size_t)z * sCz; }

    int tid = threadIdx.x, lane = tid & 31, wid = tid >> 5;
    int g = lane >> 2, tig = lane & 3;
    int wm = (wid >> 1) * 32, wn = (wid & 1) * 64;
    int m0 = blockIdx.y * 128, n0 = blockIdx.x * 128;
    int r16 = lane & 15, koff = (lane >> 4) * 8;

    bool doF = Cf  && (qkvMode == 0 || n0 >= 768);
    bool doH = Chi && (qkvMode == 0 || n0 < 768);

    float acc[2][8][4];
#pragma unroll
    for (int mt = 0; mt < 2; ++mt)
#pragma unroll
        for (int nt = 0; nt < 8; ++nt)
#pragma unroll
            for (int i = 0; i < 4; ++i) acc[mt][nt][i] = 0.f;

    auto load_chunk = [&](int kc, int s) {
        uint32_t st = sb + s * GSTG;
#pragma unroll
        for (int it = 0; it < 2; ++it) {
            int idx = tid + it * 256;
            int row = idx >> 2, seg8 = (idx & 3) * 8;
            uint32_t so = row * 80 + seg8 * 2;
            size_t ga = (size_t)(m0 + row) * lda + kc + seg8;
            size_t gb = (size_t)(n0 + row) * ldb + kc + seg8;
            cpasync16(st +         so, Ah + ga);
            cpasync16(st + 10240 + so, Al + ga);
            cpasync16(st + 20480 + so, Bh + gb);
            cpasync16(st + 30720 + so, Bl + gb);
        }
    };

    int nch = K / 32;
    load_chunk(0, 0);
    CP_COMMIT();
    for (int c = 0; c < nch; ++c) {
        int s = c & 1;
        if (c + 1 < nch) { load_chunk((c + 1) * 32, s ^ 1); CP_COMMIT(); CP_WAIT1(); }
        else CP_WAIT0();
        __syncthreads();
        uint32_t st = sb + s * GSTG;
#pragma unroll
        for (int ks = 0; ks < 2; ++ks) {
            uint32_t ah[2][4], al[2][4];
#pragma unroll
            for (int mt = 0; mt < 2; ++mt) {
                uint32_t aadr = st + (wm + mt * 16 + r16) * 80 + (ks * 16 + koff) * 2;
                ldsm4(aadr,         ah[mt][0], ah[mt][1], ah[mt][2], ah[mt][3]);
                ldsm4(aadr + 10240, al[mt][0], al[mt][1], al[mt][2], al[mt][3]);
            }
#pragma unroll
            for (int ntp = 0; ntp < 4; ++ntp) {
                uint32_t badr = st + 20480 + (wn + ntp * 16 + r16) * 80 + (ks * 16 + koff) * 2;
                uint32_t bh4[4], bl4[4];
                ldsm4(badr,         bh4[0], bh4[1], bh4[2], bh4[3]);
                ldsm4(badr + 10240, bl4[0], bl4[1], bl4[2], bl4[3]);
#pragma unroll
                for (int half = 0; half < 2; ++half) {
                    int nt = 2 * ntp + half;
                    uint32_t bh0 = bh4[half], bh1 = bh4[half + 2];
                    uint32_t bl0 = bl4[half], bl1 = bl4[half + 2];
#pragma unroll
                    for (int mt = 0; mt < 2; ++mt) {
                        MMA16(acc[mt][nt], ah[mt], bh0, bh1);
                        MMA16(acc[mt][nt], ah[mt], bl0, bl1);
                        MMA16(acc[mt][nt], al[mt], bh0, bh1);
                    }
                }
            }
        }
        __syncthreads();
    }
#pragma unroll
    for (int mt = 0; mt < 2; ++mt)
#pragma unroll
        for (int nt = 0; nt < 8; ++nt) {
            int row = m0 + wm + mt * 16 + g;
            int col = n0 + wn + nt * 8 + 2 * tig;
            float v0 = acc[mt][nt][0], v1 = acc[mt][nt][1];
            float v2 = acc[mt][nt][2], v3 = acc[mt][nt][3];
            if (bias) {
                float b0v = bias[col], b1v = bias[col + 1];
                v0 += b0v; v1 += b1v; v2 += b0v; v3 += b1v;
            }
            if (doF) {
                *(float2*)(Cf + (size_t)row * ldc + col)       = make_float2(v0, v1);
                *(float2*)(Cf + (size_t)(row + 8) * ldc + col) = make_float2(v2, v3);
            }
            if (doH) {
                uint32_t h01, h23, l01, l23;
                if (qkvMode == 1) {   // fp16 hi/lo (for attention Q)
                    h01 = packh2(v0, v1); h23 = packh2(v2, v3);
                    l01 = packh2lo(v0, v1, h01); l23 = packh2lo(v2, v3, h23);
                } else {              // bf16 hi/lo
                    h01 = packhi2(v0, v1); h23 = packhi2(v2, v3);
                    l01 = packlo2(v0, v1, h01); l23 = packlo2(v2, v3, h23);
                }
                *(uint32_t*)(Chi + (size_t)row * ldc + col)       = h01;
                *(uint32_t*)(Chi + (size_t)(row + 8) * ldc + col) = h23;
                *(uint32_t*)(Clo + (size_t)row * ldc + col)       = l01;
                *(uint32_t*)(Clo + (size_t)(row + 8) * ldc + col) = l23;
            }
        }
}

// ---------------- area pooling: K single fp16 + V single fp16 -------------
__global__ __launch_bounds__(256)
void pool_kernel() {
    int bh = blockIdx.x, cbase = blockIdx.y * 16;
    int b = bh / HEADS_, h = bh % HEADS_;
    __shared__ float sat[16][289];
    int t = threadIdx.x;
    const int cnts[9] = {256, 240, 224, 240, 225, 210, 224, 210, 196};

    for (int pass = 0; pass < 2; ++pass) {
        const float* base = g_qkvh_f + (size_t)(b * N_) * K3 + (pass ? 2 * DIM_ : DIM_)
                          + h * DHEAD_ + cbase;
        {
            int ch = t & 15, row = t >> 4;
            if (row == 0)
#pragma unroll
                for (int x = 0; x < 17; ++x) sat[ch][x] = 0.f;
            sat[ch][(row + 1) * 17] = 0.f;
            float vals[16];
#pragma unroll
            for (int x = 0; x < 16; ++x)
                vals[x] = base[(size_t)(row * 16 + x) * K3 + ch];
            float acc = 0.f;
#pragma unroll
            for (int x = 0; x < 16; ++x) {
                acc += vals[x];
                sat[ch][(row + 1) * 17 + x + 1] = acc;
            }
        }
        __syncthreads();
        {
            int ch = t >> 4, col = (t & 15) + 1;
            float acc = 0.f;
#pragma unroll
            for (int y = 1; y <= 16; ++y) {
                acc += sat[ch][y * 17 + col];
                sat[ch][y * 17 + col] = acc;
            }
        }
        __syncthreads();
        int sub = t & 1;
        for (int m = t >> 1; m < MPAD; m += 128) {
            float scale = 0.f;
            int y0 = 0, x0 = 0, ah = 1, aw = 1;
            bool valid = (m < MAREA);
            if (valid) {
                int rem = m, seg = 0;
                while (rem >= cnts[seg]) { rem -= cnts[seg]; ++seg; }
                ah = seg / 3 + 1; aw = seg % 3 + 1;
                int w = 17 - aw;
                y0 = rem / w; x0 = rem % w;
                scale = (pass == 0) ? 1.f / (float)(ah * aw) : 1.f;
            }
            int iA = (y0 + ah) * 17 + x0 + aw, iB = y0 * 17 + x0 + aw;
            int iC = (y0 + ah) * 17 + x0,      iD = y0 * 17 + x0;
            size_t o = ((size_t)bh * MPAD + m) * DHEAD_ + cbase + sub * 8;
            __half vv[8];
#pragma unroll
            for (int c = 0; c < 8; ++c) {
                int ch = sub * 8 + c;
                float s = 0.f;
                if (valid)
                    s = (sat[ch][iA] - sat[ch][iB] - sat[ch][iC] + sat[ch][iD]) * scale;
                vv[c] = __float2half(s);
            }
            if (pass == 0) *(uint4*)(g_ka_h + o) = *(uint4*)vv;
            else           *(uint4*)(g_va_h + o) = *(uint4*)vv;
        }
        __syncthreads();
    }
}

// ---------------- attention: all-fp16 MMAs (Q 2-term, K/V single) ---------
// Stage: K 0, V 9216 (64 rows x 144B each); ASTG 18432.
#define ASTG 18432
#define AQOF 36864
#define AHALF (MPAD / 2)
__global__ __launch_bounds__(256, 2)
void attn_kernel() {
    extern __shared__ char smem[];
    uint32_t sb = smem_u32(smem);
    int tid = threadIdx.x, lane = tid & 31, wid = tid >> 5;
    int g = lane >> 2, tig = lane & 3;
    int wm = wid * 16;
    int bh = blockIdx.y;
    int q0 = (blockIdx.x >> 1) * 128;
    int z = blockIdx.x & 1;
    int a0 = z * AHALF;
    int b = bh / HEADS_, h = bh % HEADS_;
    int r16 = lane & 15, koff = (lane >> 4) * 8;

    __half* Qs = (__half*)smem;
#pragma unroll
    for (int it = 0; it < 4; ++it) {
        int idx = tid + it * 256;
        int row = idx >> 3, seg = (idx & 7) * 8;
        size_t src = (size_t)(b * N_ + q0 + row) * K3 + h * 64 + seg;
        *(uint4*)(Qs + row * 72 + seg)        = *(const uint4*)(g_qkvh_hi + src);
        *(uint4*)(Qs + 9216 + row * 72 + seg) = *(const uint4*)(g_qkvh_lo + src);
    }

    const __half* kaF = g_ka_h + (size_t)bh * MPAD * 64 + (size_t)a0 * 64;
    const __half* vaF = g_va_h + (size_t)bh * MPAD * 64 + (size_t)a0 * 64;

    auto load_tile = [&](int t, int s) {
        uint32_t st = sb + AQOF + s * ASTG;
#pragma unroll
        for (int it = 0; it < 2; ++it) {
            int idx = tid + it * 256;
            int row = idx >> 3, seg = (idx & 7) * 8;
            uint32_t so = row * 144 + seg * 2;
            size_t gk = (size_t)(t * 64 + row) * 64 + seg;
            cpasync16(st +        so, kaF + gk);
            cpasync16(st + 9216 + so, vaF + gk);
        }
    };

    float accO[8][4];
#pragma unroll
    for (int nt = 0; nt < 8; ++nt)
#pragma unroll
        for (int i = 0; i < 4; ++i) accO[nt][i] = 0.f;
    float lsum[2] = {0.f, 0.f};

    const int NT = AHALF / 64;  // 16
    load_tile(0, 0);
    CP_COMMIT();
    for (int t = 0; t < NT; ++t) {
        int s = t & 1;
        if (t + 1 < NT) { load_tile(t + 1, s ^ 1); CP_COMMIT(); CP_WAIT1(); }
        else CP_WAIT0();
        __syncthreads();
        uint32_t st = sb + AQOF + s * ASTG;

        // ---- QK (fp16: Qh,Ql x K) ----
        float sc[8][4];
#pragma unroll
        for (int nt = 0; nt < 8; ++nt)
#pragma unroll
            for (int i = 0; i < 4; ++i) sc[nt][i] = 0.f;
#pragma unroll
        for (int ks = 0; ks < 4; ++ks) {
            uint32_t qh[4], ql[4];
            uint32_t qadr = sb + (wm + r16) * 144 + (ks * 16 + koff) * 2;
            ldsm4(qadr,         qh[0], qh[1], qh[2], qh[3]);
            ldsm4(qadr + 18432, ql[0], ql[1], ql[2], ql[3]);
#pragma unroll
            for (int ntp = 0; ntp < 4; ++ntp) {
                uint32_t kadr = st + (ntp * 16 + r16) * 144 + (ks * 16 + koff) * 2;
                uint32_t k4[4];
                ldsm4(kadr, k4[0], k4[1], k4[2], k4[3]);
#pragma unroll
                for (int half = 0; half < 2; ++half) {
                    int nt = 2 * ntp + half;
                    uint32_t b0 = k4[half], b1 = k4[half + 2];
                    MMA16H(sc[nt], qh, b0, b1);
                    MMA16H(sc[nt], ql, b0, b1);
                }
            }
        }

        // ---- softmax ----
        bool need_mask = (a0 + t * 64 + 64) > MAREA;
        if (need_mask) {
#pragma unroll
            for (int nt = 0; nt < 8; ++nt) {
                int cb = a0 + t * 64 + nt * 8 + 2 * tig;
                float p0 = (cb     < MAREA) ? __expf(sc[nt][0]) : 0.f;
                float p1 = (cb + 1 < MAREA) ? __expf(sc[nt][1]) : 0.f;
                float p2 = (cb     < MAREA) ? __expf(sc[nt][2]) : 0.f;
                float p3 = (cb + 1 < MAREA) ? __expf(sc[nt][3]) : 0.f;
                sc[nt][0] = p0; sc[nt][1] = p1; sc[nt][2] = p2; sc[nt][3] = p3;
                lsum[0] += p0 + p1;
                lsum[1] += p2 + p3;
            }
        } else {
#pragma unroll
            for (int nt = 0; nt < 8; ++nt) {
                float p0 = __expf(sc[nt][0]);
                float p1 = __expf(sc[nt][1]);
                float p2 = __expf(sc[nt][2]);
                float p3 = __expf(sc[nt][3]);
                sc[nt][0] = p0; sc[nt][1] = p1; sc[nt][2] = p2; sc[nt][3] = p3;
                lsum[0] += p0 + p1;
                lsum[1] += p2 + p3;
            }
        }

        // ---- PV (single fp16 MMA) ----
#pragma unroll
        for (int kk = 0; kk < 4; ++kk) {
            uint32_t pa[4];
            pa[0] = packh2(sc[2 * kk][0],     sc[2 * kk][1]);
            pa[1] = packh2(sc[2 * kk][2],     sc[2 * kk][3]);
            pa[2] = packh2(sc[2 * kk + 1][0], sc[2 * kk + 1][1]);
            pa[3] = packh2(sc[2 * kk + 1][2], sc[2 * kk + 1][3]);
#pragma unroll
            for (int ntp = 0; ntp < 4; ++ntp) {
                uint32_t vadr = st + 9216 + (kk * 16 + r16) * 144 + (ntp * 16 + koff) * 2;
                uint32_t vh4[4];
                ldsm4t(vadr, vh4[0], vh4[1], vh4[2], vh4[3]);
#pragma unroll
                for (int half = 0; half < 2; ++half) {
                    int nt = 2 * ntp + half;
                    MMA16H(accO[nt], pa, vh4[half * 2], vh4[half * 2 + 1]);
                }
            }
        }
        __syncthreads();
    }

    // ---- write unnormalized partials ----
#pragma unroll
    for (int r = 0; r < 2; ++r) {
        lsum[r] += __shfl_xor_sync(0xFFFFFFFF, lsum[r], 1);
        lsum[r] += __shfl_xor_sync(0xFFFFFFFF, lsum[r], 2);
    }
    int row0 = b * N_ + q0 + wm + g;
    size_t obase = (size_t)z * ROWS_ * DIM_;
    size_t orow0 = obase + (size_t)row0 * DIM_ + h * 64;
    size_t orow1 = obase + (size_t)(row0 + 8) * DIM_ + h * 64;
#pragma unroll
    for (int nt = 0; nt < 8; ++nt) {
        int cc = nt * 8 + 2 * tig;
        *(float2*)(g_Opart + orow0 + cc) = make_float2(accO[nt][0], accO[nt][1]);
        *(float2*)(g_Opart + orow1 + cc) = make_float2(accO[nt][2], accO[nt][3]);
    }
    if (tig == 0) {
        g_lpart[z * ROWS_ * HEADS_ + row0 * HEADS_ + h]       = lsum[0];
        g_lpart[z * ROWS_ * HEADS_ + (row0 + 8) * HEADS_ + h] = lsum[1];
    }
}

// ---------------- combine: (O0+O1)/(l0+l1) -> attn hi/lo ------------------
__global__ __launch_bounds__(256)
void combine_kernel() {
    int i = blockIdx.x * 256 + threadIdx.x;
    int e = i * 2;
    int row = e / DIM_, col = e % DIM_;
    int h = col >> 6;
    float l = g_lpart[row * HEADS_ + h] + g_lpart[ROWS_ * HEADS_ + row * HEADS_ + h];
    float inv = 1.f / l;
    float2 a = *(float2*)(g_Opart + e);
    float2 bb = *(float2*)(g_Opart + (size_t)ROWS_ * DIM_ + e);
    float o0 = (a.x + bb.x) * inv, o1 = (a.y + bb.y) * inv;
    uint32_t h01 = packhi2(o0, o1);
    *(uint32_t*)(g_attn_hi + e) = h01;
    *(uint32_t*)(g_attn_lo + e) = packlo2(o0, o1, h01);
}

// ---------------- launch ---------------------------------------------------
extern "C" void kernel_launch(void* const* d_in, const int* in_sizes, int n_in,
                              void* d_out, int out_size) {
    const float* x     = (const float*)d_in[0];
    const float* w_qkv = (const float*)d_in[1];
    const float* w_q   = (const float*)d_in[2];
    const float* b_q   = (const float*)d_in[3];
    const float* w_k   = (const float*)d_in[4];
    const float* b_k   = (const float*)d_in[5];
    const float* w_v   = (const float*)d_in[6];
    const float* b_v   = (const float*)d_in[7];
    const float* w_o   = (const float*)d_in[8];
    const float* b_o   = (const float*)d_in[9];
    float* out = (float*)d_out;

    cudaFuncSetAttribute(gemm128_kernel, cudaFuncAttributeMaxDynamicSharedMemorySize, 2 * GSTG);
    cudaFuncSetAttribute(attn_kernel,    cudaFuncAttributeMaxDynamicSharedMemorySize, AQOF + 2 * ASTG);

    bf16 *x_hi, *x_lo, *wqkv_hi, *wqkv_lo, *wT_hi, *wT_lo, *woT_hi, *woT_lo;
    bf16 *weffT_hi, *weffT_lo, *qkvh_hi, *qkvh_lo, *attn_hi, *attn_lo;
    float *qkvh_f, *biasqkv;
    cudaGetSymbolAddress((void**)&x_hi, g_x_hi);       cudaGetSymbolAddress((void**)&x_lo, g_x_lo);
    cudaGetSymbolAddress((void**)&wqkv_hi, g_wqkv_hi); cudaGetSymbolAddress((void**)&wqkv_lo, g_wqkv_lo);
    cudaGetSymbolAddress((void**)&wT_hi, g_wT_hi);     cudaGetSymbolAddress((void**)&wT_lo, g_wT_lo);
    cudaGetSymbolAddress((void**)&woT_hi, g_woT_hi);   cudaGetSymbolAddress((void**)&woT_lo, g_woT_lo);
    cudaGetSymbolAddress((void**)&weffT_hi, g_weffT_hi); cudaGetSymbolAddress((void**)&weffT_lo, g_weffT_lo);
    cudaGetSymbolAddress((void**)&qkvh_f, g_qkvh_f);
    cudaGetSymbolAddress((void**)&qkvh_hi, g_qkvh_hi); cudaGetSymbolAddress((void**)&qkvh_lo, g_qkvh_lo);
    cudaGetSymbolAddress((void**)&attn_hi, g_attn_hi); cudaGetSymbolAddress((void**)&attn_lo, g_attn_lo);
    cudaGetSymbolAddress((void**)&biasqkv, g_biasqkv);

    // 1. fused prep
    prep_kernel<<<NB_CONVX4 + NB_CONVW4 + NB_CONVT + 9, 256>>>(
        x, w_qkv, w_q, w_k, w_v, w_o, b_q, b_k, b_v);

    // 2. compose W_eff^T (bf16 hi/lo out)
    {
        dim3 g(6, 6, 3);
        gemm128_kernel<<<g, 256, 2 * GSTG>>>(
            wT_hi, wT_lo, DIM_, wqkv_hi, wqkv_lo, K3,
            nullptr, weffT_hi, weffT_lo, DIM_, DIM_, nullptr,
            DIM_ * DIM_, DIM_, DIM_ * DIM_, 0);
    }

    // 3. qh|kh|vh = x @ W_eff + bias (q cols: fp16 hi/lo; k/v cols: f32)
    {
        dim3 g(K3 / 128, ROWS_ / 128, 1);
        gemm128_kernel<<<g, 256, 2 * GSTG>>>(x_hi, x_lo, DIM_, weffT_hi, weffT_lo, DIM_,
                                             qkvh_f, qkvh_hi, qkvh_lo, K3, DIM_, biasqkv,
                                             0, 0, 0, 1);
    }

    // 4. area pooling (K and V single fp16)
    {
        dim3 g(BH_, 4);
        pool_kernel<<<g, 256>>>();
    }

    // 5. attention (bh-major grid)
    {
        dim3 g(4, BH_);
        attn_kernel<<<g, 256, AQOF + 2 * ASTG>>>();
    }

    // 6. combine partials
    combine_kernel<<<ROWS_ * DIM_ / 512, 256>>>();

    // 7. out = attn @ w_o + b_o
    {
        dim3 g(DIM_ / 128, ROWS_ / 128, 1);
        gemm128_kernel<<<g, 256, 2 * GSTG>>>(attn_hi, attn_lo, DIM_, woT_hi, woT_lo, DIM_,
                                             out, nullptr, nullptr, DIM_, DIM_, b_o,
                                             0, 0, 0, 0);
    }
}

// round 17
// speedup vs baseline: 1.4749x; 1.1527x over previous
#include <cuda_runtime.h>
#include <cuda_bf16.h>
#include <cuda_fp16.h>
#include <cstdint>

#define B_     16
#define N_     256
#define DIM_   768
#define HEADS_ 12
#define DHEAD_ 64
#define BH_    192
#define MAREA  2025
#define MPAD   2048
#define ROWS_  4096
#define K3     2304

typedef __nv_bfloat16 bf16;

// ---------------- device global scratch ----------------
__device__ float g_biasqkv[K3];
__device__ __half g_xh_hi[ROWS_*DIM_], g_xh_lo[ROWS_*DIM_];      // x fp16 hi/lo
__device__ bf16  g_wqkv_hi[DIM_*K3],   g_wqkv_lo[DIM_*K3];
__device__ bf16  g_wT_hi[3*DIM_*DIM_], g_wT_lo[3*DIM_*DIM_];
__device__ bf16  g_woT_hi[DIM_*DIM_],  g_woT_lo[DIM_*DIM_];
__device__ __half g_weffT_h[K3*DIM_];                            // W_eff fp16 single
__device__ float g_qkvh_f[(size_t)ROWS_*K3];
__device__ __half g_q_h[(size_t)ROWS_*K3];   // q cols hold fp16 single Q
__device__ __half g_ka_h[(size_t)BH_*MPAD*DHEAD_];
__device__ __half g_va_h[(size_t)BH_*MPAD*DHEAD_];
__device__ bf16  g_attn_hi[(size_t)ROWS_*DIM_], g_attn_lo[(size_t)ROWS_*DIM_];
__device__ float g_Opart[(size_t)2*ROWS_*DIM_];
__device__ float g_lpart[2*ROWS_*HEADS_];

// ---------------- helpers ----------------
__device__ __forceinline__ uint32_t smem_u32(const void* p) {
    uint32_t a;
    asm("{ .reg .u64 t; cvta.to.shared.u64 t, %1; cvt.u32.u64 %0, t; }" : "=r"(a) : "l"(p));
    return a;
}
__device__ __forceinline__ uint32_t packhi2(float x, float y) {
    __nv_bfloat162 t = __floats2bfloat162_rn(x, y);
    return *(uint32_t*)&t;
}
__device__ __forceinline__ uint32_t packlo2(float x, float y, uint32_t hp) {
    __nv_bfloat162 h = *(__nv_bfloat162*)&hp;
    __nv_bfloat162 t = __floats2bfloat162_rn(x - __bfloat162float(h.x),
                                             y - __bfloat162float(h.y));
    return *(uint32_t*)&t;
}
__device__ __forceinline__ uint32_t packh2(float x, float y) {
    __half2 t = __floats2half2_rn(x, y);
    return *(uint32_t*)&t;
}
__device__ __forceinline__ uint32_t packh2lo(float x, float y, uint32_t hp) {
    __half2 h = *(__half2*)&hp;
    __half2 t = __floats2half2_rn(x - __half2float(h.x), y - __half2float(h.y));
    return *(uint32_t*)&t;
}

#define MMA16(d, a, b0, b1) \
    asm volatile("mma.sync.aligned.m16n8k16.row.col.f32.bf16.bf16.f32 " \
        "{%0,%1,%2,%3}, {%4,%5,%6,%7}, {%8,%9}, {%0,%1,%2,%3};" \
        : "+f"((d)[0]), "+f"((d)[1]), "+f"((d)[2]), "+f"((d)[3]) \
        : "r"((a)[0]), "r"((a)[1]), "r"((a)[2]), "r"((a)[3]), "r"(b0), "r"(b1))

#define MMA16H(d, a, b0, b1) \
    asm volatile("mma.sync.aligned.m16n8k16.row.col.f32.f16.f16.f32 " \
        "{%0,%1,%2,%3}, {%4,%5,%6,%7}, {%8,%9}, {%0,%1,%2,%3};" \
        : "+f"((d)[0]), "+f"((d)[1]), "+f"((d)[2]), "+f"((d)[3]) \
        : "r"((a)[0]), "r"((a)[1]), "r"((a)[2]), "r"((a)[3]), "r"(b0), "r"(b1))

__device__ __forceinline__ void ldsm4(uint32_t addr, uint32_t& r0, uint32_t& r1,
                                      uint32_t& r2, uint32_t& r3) {
    asm volatile("ldmatrix.sync.aligned.m8n8.x4.shared.b16 {%0,%1,%2,%3}, [%4];"
                 : "=r"(r0), "=r"(r1), "=r"(r2), "=r"(r3) : "r"(addr));
}
__device__ __forceinline__ void ldsm4t(uint32_t addr, uint32_t& r0, uint32_t& r1,
                                       uint32_t& r2, uint32_t& r3) {
    asm volatile("ldmatrix.sync.aligned.m8n8.x4.trans.shared.b16 {%0,%1,%2,%3}, [%4];"
                 : "=r"(r0), "=r"(r1), "=r"(r2), "=r"(r3) : "r"(addr));
}
__device__ __forceinline__ void cpasync16(uint32_t saddr, const void* g) {
    asm volatile("cp.async.cg.shared.global [%0], [%1], 16;" :: "r"(saddr), "l"(g));
}
#define CP_COMMIT() asm volatile("cp.async.commit_group;" ::: "memory")
#define CP_WAIT0()  asm volatile("cp.async.wait_group 0;" ::: "memory")
#define CP_WAIT1()  asm volatile("cp.async.wait_group 1;" ::: "memory")

// ---------------- fused prep kernel ---------------------------------------
#define NB_CONVX4 3072
#define NB_CONVW4 1728
#define NB_CONVT  2304
__global__ __launch_bounds__(256)
void prep_kernel(const float* __restrict__ x, const float* __restrict__ w_qkv,
                 const float* __restrict__ w_q, const float* __restrict__ w_k,
                 const float* __restrict__ w_v, const float* __restrict__ w_o,
                 const float* __restrict__ bq, const float* __restrict__ bk,
                 const float* __restrict__ bv) {
    __shared__ float tile[32][33];
    int bx = blockIdx.x, t = threadIdx.x;
    if (bx < NB_CONVX4) {
        // x -> fp16 hi/lo
        int i = (bx * 256 + t) * 4;
        float4 v = *(const float4*)(x + i);
        uint32_t h01 = packh2(v.x, v.y), h23 = packh2(v.z, v.w);
        uint32_t l01 = packh2lo(v.x, v.y, h01), l23 = packh2lo(v.z, v.w, h23);
        *(uint2*)(g_xh_hi + i) = make_uint2(h01, h23);
        *(uint2*)(g_xh_lo + i) = make_uint2(l01, l23);
    } else if (bx < NB_CONVX4 + NB_CONVW4) {
        int i = ((bx - NB_CONVX4) * 256 + t) * 4;
        float4 v = *(const float4*)(w_qkv + i);
        uint32_t h01 = packhi2(v.x, v.y), h23 = packhi2(v.z, v.w);
        uint32_t l01 = packlo2(v.x, v.y, h01), l23 = packlo2(v.z, v.w, h23);
        *(uint2*)(g_wqkv_hi + i) = make_uint2(h01, h23);
        *(uint2*)(g_wqkv_lo + i) = make_uint2(l01, l23);
    } else if (bx < NB_CONVX4 + NB_CONVW4 + NB_CONVT) {
        int id = bx - (NB_CONVX4 + NB_CONVW4);
        int seg = id / 576, rem = id % 576;
        int c0 = (rem % 24) * 32, r0 = (rem / 24) * 32;
        const float* src = (seg == 0) ? w_q : (seg == 1) ? w_k : (seg == 2) ? w_v : w_o;
        bf16* hi = (seg < 3) ? (g_wT_hi + (size_t)seg * DIM_ * DIM_) : g_woT_hi;
        bf16* lo = (seg < 3) ? (g_wT_lo + (size_t)seg * DIM_ * DIM_) : g_woT_lo;
        int tx = t & 31, ty = t >> 5;
#pragma unroll
        for (int i = 0; i < 4; ++i)
            tile[ty + i * 8][tx] = src[(size_t)(r0 + ty + i * 8) * DIM_ + c0 + tx];
        __syncthreads();
#pragma unroll
        for (int i = 0; i < 4; ++i) {
            float v = tile[tx][ty + i * 8];
            size_t o = (size_t)(c0 + ty + i * 8) * DIM_ + r0 + tx;
            bf16 h = __float2bfloat16(v);
            hi[o] = h;
            lo[o] = __float2bfloat16(v - __bfloat162float(h));
        }
    } else {
        int idx = (bx - (NB_CONVX4 + NB_CONVW4 + NB_CONVT)) * 256 + t;
        int seg = idx / 768;
        const float* s = (seg == 0) ? bq : (seg == 1) ? bk : bv;
        g_biasqkv[idx] = s[idx % 768];
    }
}

// ---------------- 128x128 warp-MMA GEMM -----------------------------------
// fmode 0: bf16 3-term (Ah,Al,Bh,Bl). fmode 1: fp16 2-term (Ah,Al x Bh).
// fp16out: Chi gets packed fp16 single (no Clo); else bf16 hi/lo pair.
#define GSTG 40960
__global__ __launch_bounds__(256, 2)
void gemm128_kernel(const bf16* __restrict__ Ah, const bf16* __restrict__ Al, int lda,
                    const bf16* __restrict__ Bh, const bf16* __restrict__ Bl, int ldb,
                    float* __restrict__ Cf, bf16* __restrict__ Chi, bf16* __restrict__ Clo,
                    int ldc, int K, const float* __restrict__ bias,
                    int sAz, int sBz, int sCz, int qkvMode, int fmode, int fp16out) {
    extern __shared__ char smem[];
    uint32_t sb = smem_u32(smem);
    int z = blockIdx.z;
    Ah += (size_t)z * sAz; Al += (size_t)z * sAz;
    Bh += (size_t)z * sBz; if (Bl) Bl += (size_t)z * sBz;
    if (Cf)  Cf  += (size_t)z * sCz;
    if (Chi) { Chi += (size_t)z * sCz; if (Clo) Clo += (size_t)z * sCz; }

    int tid = threadIdx.x, lane = tid & 31, wid = tid >> 5;
    int g = lane >> 2, tig = lane & 3;
    int wm = (wid >> 1) * 32, wn = (wid & 1) * 64;
    int m0 = blockIdx.y * 128, n0 = blockIdx.x * 128;
    int r16 = lane & 15, koff = (lane >> 4) * 8;

    bool doF = Cf  && (qkvMode == 0 || n0 >= 768);
    bool doH = Chi && (qkvMode == 0 || n0 < 768);

    float acc[2][8][4];
#pragma unroll
    for (int mt = 0; mt < 2; ++mt)
#pragma unroll
        for (int nt = 0; nt < 8; ++nt)
#pragma unroll
            for (int i = 0; i < 4; ++i) acc[mt][nt][i] = 0.f;

    auto load_chunk = [&](int kc, int s) {
        uint32_t st = sb + s * GSTG;
#pragma unroll
        for (int it = 0; it < 2; ++it) {
            int idx = tid + it * 256;
            int row = idx >> 2, seg8 = (idx & 3) * 8;
            uint32_t so = row * 80 + seg8 * 2;
            size_t ga = (size_t)(m0 + row) * lda + kc + seg8;
            size_t gb = (size_t)(n0 + row) * ldb + kc + seg8;
            cpasync16(st +         so, Ah + ga);
            cpasync16(st + 10240 + so, Al + ga);
            cpasync16(st + 20480 + so, Bh + gb);
            if (fmode == 0) cpasync16(st + 30720 + so, Bl + gb);
        }
    };

    int nch = K / 32;
    load_chunk(0, 0);
    CP_COMMIT();
    for (int c = 0; c < nch; ++c) {
        int s = c & 1;
        if (c + 1 < nch) { load_chunk((c + 1) * 32, s ^ 1); CP_COMMIT(); CP_WAIT1(); }
        else CP_WAIT0();
        __syncthreads();
        uint32_t st = sb + s * GSTG;
#pragma unroll
        for (int ks = 0; ks < 2; ++ks) {
            uint32_t ah[2][4], al[2][4];
#pragma unroll
            for (int mt = 0; mt < 2; ++mt) {
                uint32_t aadr = st + (wm + mt * 16 + r16) * 80 + (ks * 16 + koff) * 2;
                ldsm4(aadr,         ah[mt][0], ah[mt][1], ah[mt][2], ah[mt][3]);
                ldsm4(aadr + 10240, al[mt][0], al[mt][1], al[mt][2], al[mt][3]);
            }
#pragma unroll
            for (int ntp = 0; ntp < 4; ++ntp) {
                uint32_t badr = st + 20480 + (wn + ntp * 16 + r16) * 80 + (ks * 16 + koff) * 2;
                uint32_t bh4[4];
                ldsm4(badr, bh4[0], bh4[1], bh4[2], bh4[3]);
                if (fmode == 0) {
                    uint32_t bl4[4];
                    ldsm4(badr + 10240, bl4[0], bl4[1], bl4[2], bl4[3]);
#pragma unroll
                    for (int half = 0; half < 2; ++half) {
                        int nt = 2 * ntp + half;
                        uint32_t bh0 = bh4[half], bh1 = bh4[half + 2];
                        uint32_t bl0 = bl4[half], bl1 = bl4[half + 2];
#pragma unroll
                        for (int mt = 0; mt < 2; ++mt) {
                            MMA16(acc[mt][nt], ah[mt], bh0, bh1);
                            MMA16(acc[mt][nt], ah[mt], bl0, bl1);
                            MMA16(acc[mt][nt], al[mt], bh0, bh1);
                        }
                    }
                } else {
#pragma unroll
                    for (int half = 0; half < 2; ++half) {
                        int nt = 2 * ntp + half;
                        uint32_t bh0 = bh4[half], bh1 = bh4[half + 2];
#pragma unroll
                        for (int mt = 0; mt < 2; ++mt) {
                            MMA16H(acc[mt][nt], ah[mt], bh0, bh1);
                            MMA16H(acc[mt][nt], al[mt], bh0, bh1);
                        }
                    }
                }
            }
        }
        __syncthreads();
    }
#pragma unroll
    for (int mt = 0; mt < 2; ++mt)
#pragma unroll
        for (int nt = 0; nt < 8; ++nt) {
            int row = m0 + wm + mt * 16 + g;
            int col = n0 + wn + nt * 8 + 2 * tig;
            float v0 = acc[mt][nt][0], v1 = acc[mt][nt][1];
            float v2 = acc[mt][nt][2], v3 = acc[mt][nt][3];
            if (bias) {
                float b0v = bias[col], b1v = bias[col + 1];
                v0 += b0v; v1 += b1v; v2 += b0v; v3 += b1v;
            }
            if (doF) {
                *(float2*)(Cf + (size_t)row * ldc + col)       = make_float2(v0, v1);
                *(float2*)(Cf + (size_t)(row + 8) * ldc + col) = make_float2(v2, v3);
            }
            if (doH) {
                if (fp16out) {
                    *(uint32_t*)(Chi + (size_t)row * ldc + col)       = packh2(v0, v1);
                    *(uint32_t*)(Chi + (size_t)(row + 8) * ldc + col) = packh2(v2, v3);
                } else {
                    uint32_t h01 = packhi2(v0, v1), h23 = packhi2(v2, v3);
                    *(uint32_t*)(Chi + (size_t)row * ldc + col)       = h01;
                    *(uint32_t*)(Chi + (size_t)(row + 8) * ldc + col) = h23;
                    *(uint32_t*)(Clo + (size_t)row * ldc + col)       = packlo2(v0, v1, h01);
                    *(uint32_t*)(Clo + (size_t)(row + 8) * ldc + col) = packlo2(v2, v3, h23);
                }
            }
        }
}

// ---------------- area pooling: K + V single fp16 --------------------------
__global__ __launch_bounds__(256)
void pool_kernel() {
    int bh = blockIdx.x, cbase = blockIdx.y * 16;
    int b = bh / HEADS_, h = bh % HEADS_;
    __shared__ float sat[16][289];
    int t = threadIdx.x;
    const int cnts[9] = {256, 240, 224, 240, 225, 210, 224, 210, 196};

    for (int pass = 0; pass < 2; ++pass) {
        const float* base = g_qkvh_f + (size_t)(b * N_) * K3 + (pass ? 2 * DIM_ : DIM_)
                          + h * DHEAD_ + cbase;
        {
            int ch = t & 15, row = t >> 4;
            if (row == 0)
#pragma unroll
                for (int x = 0; x < 17; ++x) sat[ch][x] = 0.f;
            sat[ch][(row + 1) * 17] = 0.f;
            float vals[16];
#pragma unroll
            for (int x = 0; x < 16; ++x)
                vals[x] = base[(size_t)(row * 16 + x) * K3 + ch];
            float acc = 0.f;
#pragma unroll
            for (int x = 0; x < 16; ++x) {
                acc += vals[x];
                sat[ch][(row + 1) * 17 + x + 1] = acc;
            }
        }
        __syncthreads();
        {
            int ch = t >> 4, col = (t & 15) + 1;
            float acc = 0.f;
#pragma unroll
            for (int y = 1; y <= 16; ++y) {
                acc += sat[ch][y * 17 + col];
                sat[ch][y * 17 + col] = acc;
            }
        }
        __syncthreads();
        int sub = t & 1;
        for (int m = t >> 1; m < MPAD; m += 128) {
            float scale = 0.f;
            int y0 = 0, x0 = 0, ah = 1, aw = 1;
            bool valid = (m < MAREA);
            if (valid) {
                int rem = m, seg = 0;
                while (rem >= cnts[seg]) { rem -= cnts[seg]; ++seg; }
                ah = seg / 3 + 1; aw = seg % 3 + 1;
                int w = 17 - aw;
                y0 = rem / w; x0 = rem % w;
                scale = (pass == 0) ? 1.f / (float)(ah * aw) : 1.f;
            }
            int iA = (y0 + ah) * 17 + x0 + aw, iB = y0 * 17 + x0 + aw;
            int iC = (y0 + ah) * 17 + x0,      iD = y0 * 17 + x0;
            size_t o = ((size_t)bh * MPAD + m) * DHEAD_ + cbase + sub * 8;
            __half vv[8];
#pragma unroll
            for (int c = 0; c < 8; ++c) {
                int ch = sub * 8 + c;
                float s = 0.f;
                if (valid)
                    s = (sat[ch][iA] - sat[ch][iB] - sat[ch][iC] + sat[ch][iD]) * scale;
                vv[c] = __float2half(s);
            }
            if (pass == 0) *(uint4*)(g_ka_h + o) = *(uint4*)vv;
            else           *(uint4*)(g_va_h + o) = *(uint4*)vv;
        }
        __syncthreads();
    }
}

// ---------------- attention: all single-fp16 MMAs --------------------------
// Q region 18432 B; stage {K 0, V 9216}, ASTG 18432.
#define ASTG 18432
#define AQOF 18432
#define AHALF (MPAD / 2)
__global__ __launch_bounds__(256, 2)
void attn_kernel() {
    extern __shared__ char smem[];
    uint32_t sb = smem_u32(smem);
    int tid = threadIdx.x, lane = tid & 31, wid = tid >> 5;
    int g = lane >> 2, tig = lane & 3;
    int wm = wid * 16;
    int bh = blockIdx.y;
    int q0 = (blockIdx.x >> 1) * 128;
    int z = blockIdx.x & 1;
    int a0 = z * AHALF;
    int b = bh / HEADS_, h = bh % HEADS_;
    int r16 = lane & 15, koff = (lane >> 4) * 8;

    __half* Qs = (__half*)smem;
#pragma unroll
    for (int it = 0; it < 4; ++it) {
        int idx = tid + it * 256;
        int row = idx >> 3, seg = (idx & 7) * 8;
        size_t src = (size_t)(b * N_ + q0 + row) * K3 + h * 64 + seg;
        *(uint4*)(Qs + row * 72 + seg) = *(const uint4*)(g_q_h + src);
    }

    const __half* kaF = g_ka_h + (size_t)bh * MPAD * 64 + (size_t)a0 * 64;
    const __half* vaF = g_va_h + (size_t)bh * MPAD * 64 + (size_t)a0 * 64;

    auto load_tile = [&](int t, int s) {
        uint32_t st = sb + AQOF + s * ASTG;
#pragma unroll
        for (int it = 0; it < 2; ++it) {
            int idx = tid + it * 256;
            int row = idx >> 3, seg = (idx & 7) * 8;
            uint32_t so = row * 144 + seg * 2;
            size_t gk = (size_t)(t * 64 + row) * 64 + seg;
            cpasync16(st +        so, kaF + gk);
            cpasync16(st + 9216 + so, vaF + gk);
        }
    };

    float accO[8][4];
#pragma unroll
    for (int nt = 0; nt < 8; ++nt)
#pragma unroll
        for (int i = 0; i < 4; ++i) accO[nt][i] = 0.f;
    float lsum[2] = {0.f, 0.f};

    const int NT = AHALF / 64;  // 16
    load_tile(0, 0);
    CP_COMMIT();
    for (int t = 0; t < NT; ++t) {
        int s = t & 1;
        if (t + 1 < NT) { load_tile(t + 1, s ^ 1); CP_COMMIT(); CP_WAIT1(); }
        else CP_WAIT0();
        __syncthreads();
        uint32_t st = sb + AQOF + s * ASTG;

        // ---- QK (single fp16) ----
        float sc[8][4];
#pragma unroll
        for (int nt = 0; nt < 8; ++nt)
#pragma unroll
            for (int i = 0; i < 4; ++i) sc[nt][i] = 0.f;
#pragma unroll
        for (int ks = 0; ks < 4; ++ks) {
            uint32_t qh[4];
            uint32_t qadr = sb + (wm + r16) * 144 + (ks * 16 + koff) * 2;
            ldsm4(qadr, qh[0], qh[1], qh[2], qh[3]);
#pragma unroll
            for (int ntp = 0; ntp < 4; ++ntp) {
                uint32_t kadr = st + (ntp * 16 + r16) * 144 + (ks * 16 + koff) * 2;
                uint32_t k4[4];
                ldsm4(kadr, k4[0], k4[1], k4[2], k4[3]);
#pragma unroll
                for (int half = 0; half < 2; ++half) {
                    int nt = 2 * ntp + half;
                    MMA16H(sc[nt], qh, k4[half], k4[half + 2]);
                }
            }
        }

        // ---- softmax ----
        bool need_mask = (a0 + t * 64 + 64) > MAREA;
        if (need_mask) {
#pragma unroll
            for (int nt = 0; nt < 8; ++nt) {
                int cb = a0 + t * 64 + nt * 8 + 2 * tig;
                float p0 = (cb     < MAREA) ? __expf(sc[nt][0]) : 0.f;
                float p1 = (cb + 1 < MAREA) ? __expf(sc[nt][1]) : 0.f;
                float p2 = (cb     < MAREA) ? __expf(sc[nt][2]) : 0.f;
                float p3 = (cb + 1 < MAREA) ? __expf(sc[nt][3]) : 0.f;
                sc[nt][0] = p0; sc[nt][1] = p1; sc[nt][2] = p2; sc[nt][3] = p3;
                lsum[0] += p0 + p1;
                lsum[1] += p2 + p3;
            }
        } else {
#pragma unroll
            for (int nt = 0; nt < 8; ++nt) {
                float p0 = __expf(sc[nt][0]);
                float p1 = __expf(sc[nt][1]);
                float p2 = __expf(sc[nt][2]);
                float p3 = __expf(sc[nt][3]);
                sc[nt][0] = p0; sc[nt][1] = p1; sc[nt][2] = p2; sc[nt][3] = p3;
                lsum[0] += p0 + p1;
                lsum[1] += p2 + p3;
            }
        }

        // ---- PV (single fp16) ----
#pragma unroll
        for (int kk = 0; kk < 4; ++kk) {
            uint32_t pa[4];
            pa[0] = packh2(sc[2 * kk][0],     sc[2 * kk][1]);
            pa[1] = packh2(sc[2 * kk][2],     sc[2 * kk][3]);
            pa[2] = packh2(sc[2 * kk + 1][0], sc[2 * kk + 1][1]);
            pa[3] = packh2(sc[2 * kk + 1][2], sc[2 * kk + 1][3]);
#pragma unroll
            for (int ntp = 0; ntp < 4; ++ntp) {
                uint32_t vadr = st + 9216 + (kk * 16 + r16) * 144 + (ntp * 16 + koff) * 2;
                uint32_t vh4[4];
                ldsm4t(vadr, vh4[0], vh4[1], vh4[2], vh4[3]);
#pragma unroll
                for (int half = 0; half < 2; ++half) {
                    int nt = 2 * ntp + half;
                    MMA16H(accO[nt], pa, vh4[half * 2], vh4[half * 2 + 1]);
                }
            }
        }
        __syncthreads();
    }

    // ---- write unnormalized partials ----
#pragma unroll
    for (int r = 0; r < 2; ++r) {
        lsum[r] += __shfl_xor_sync(0xFFFFFFFF, lsum[r], 1);
        lsum[r] += __shfl_xor_sync(0xFFFFFFFF, lsum[r], 2);
    }
    int row0 = b * N_ + q0 + wm + g;
    size_t obase = (size_t)z * ROWS_ * DIM_;
    size_t orow0 = obase + (size_t)row0 * DIM_ + h * 64;
    size_t orow1 = obase + (size_t)(row0 + 8) * DIM_ + h * 64;
#pragma unroll
    for (int nt = 0; nt < 8; ++nt) {
        int cc = nt * 8 + 2 * tig;
        *(float2*)(g_Opart + orow0 + cc) = make_float2(accO[nt][0], accO[nt][1]);
        *(float2*)(g_Opart + orow1 + cc) = make_float2(accO[nt][2], accO[nt][3]);
    }
    if (tig == 0) {
        g_lpart[z * ROWS_ * HEADS_ + row0 * HEADS_ + h]       = lsum[0];
        g_lpart[z * ROWS_ * HEADS_ + (row0 + 8) * HEADS_ + h] = lsum[1];
    }
}

// ---------------- combine ---------------------------------------------------
__global__ __launch_bounds__(256)
void combine_kernel() {
    int i = blockIdx.x * 256 + threadIdx.x;
    int e = i * 2;
    int row = e / DIM_, col = e % DIM_;
    int h = col >> 6;
    float l = g_lpart[row * HEADS_ + h] + g_lpart[ROWS_ * HEADS_ + row * HEADS_ + h];
    float inv = 1.f / l;
    float2 a = *(float2*)(g_Opart + e);
    float2 bb = *(float2*)(g_Opart + (size_t)ROWS_ * DIM_ + e);
    float o0 = (a.x + bb.x) * inv, o1 = (a.y + bb.y) * inv;
    uint32_t h01 = packhi2(o0, o1);
    *(uint32_t*)(g_attn_hi + e) = h01;
    *(uint32_t*)(g_attn_lo + e) = packlo2(o0, o1, h01);
}

// ---------------- launch ---------------------------------------------------
extern "C" void kernel_launch(void* const* d_in, const int* in_sizes, int n_in,
                              void* d_out, int out_size) {
    const float* x     = (const float*)d_in[0];
    const float* w_qkv = (const float*)d_in[1];
    const float* w_q   = (const float*)d_in[2];
    const float* b_q   = (const float*)d_in[3];
    const float* w_k   = (const float*)d_in[4];
    const float* b_k   = (const float*)d_in[5];
    const float* w_v   = (const float*)d_in[6];
    const float* b_v   = (const float*)d_in[7];
    const float* w_o   = (const float*)d_in[8];
    const float* b_o   = (const float*)d_in[9];
    float* out = (float*)d_out;

    cudaFuncSetAttribute(gemm128_kernel, cudaFuncAttributeMaxDynamicSharedMemorySize, 2 * GSTG);
    cudaFuncSetAttribute(attn_kernel,    cudaFuncAttributeMaxDynamicSharedMemorySize, AQOF + 2 * ASTG);

    bf16 *wqkv_hi, *wqkv_lo, *wT_hi, *wT_lo, *woT_hi, *woT_lo, *attn_hi, *attn_lo;
    __half *xh_hi, *xh_lo, *weffT_h, *q_h;
    float *qkvh_f, *biasqkv;
    cudaGetSymbolAddress((void**)&xh_hi, g_xh_hi);     cudaGetSymbolAddress((void**)&xh_lo, g_xh_lo);
    cudaGetSymbolAddress((void**)&wqkv_hi, g_wqkv_hi); cudaGetSymbolAddress((void**)&wqkv_lo, g_wqkv_lo);
    cudaGetSymbolAddress((void**)&wT_hi, g_wT_hi);     cudaGetSymbolAddress((void**)&wT_lo, g_wT_lo);
    cudaGetSymbolAddress((void**)&woT_hi, g_woT_hi);   cudaGetSymbolAddress((void**)&woT_lo, g_woT_lo);
    cudaGetSymbolAddress((void**)&weffT_h, g_weffT_h);
    cudaGetSymbolAddress((void**)&qkvh_f, g_qkvh_f);
    cudaGetSymbolAddress((void**)&q_h, g_q_h);
    cudaGetSymbolAddress((void**)&attn_hi, g_attn_hi); cudaGetSymbolAddress((void**)&attn_lo, g_attn_lo);
    cudaGetSymbolAddress((void**)&biasqkv, g_biasqkv);

    // 1. fused prep (x -> fp16 hi/lo; weights -> bf16 hi/lo)
    prep_kernel<<<NB_CONVX4 + NB_CONVW4 + NB_CONVT + 9, 256>>>(
        x, w_qkv, w_q, w_k, w_v, w_o, b_q, b_k, b_v);

    // 2. compose W_eff^T -> fp16 single
    {
        dim3 g(6, 6, 3);
        gemm128_kernel<<<g, 256, 2 * GSTG>>>(
            wT_hi, wT_lo, DIM_, wqkv_hi, wqkv_lo, K3,
            nullptr, (bf16*)weffT_h, nullptr, DIM_, DIM_, nullptr,
            DIM_ * DIM_, DIM_, DIM_ * DIM_, 0, 0, 1);
    }

    // 3. qkv = x @ W_eff + bias (fp16 2-term; q cols -> fp16 single, k/v -> f32)
    {
        dim3 g(K3 / 128, ROWS_ / 128, 1);
        gemm128_kernel<<<g, 256, 2 * GSTG>>>(
            (bf16*)xh_hi, (bf16*)xh_lo, DIM_, (bf16*)weffT_h, nullptr, DIM_,
            qkvh_f, (bf16*)q_h, nullptr, K3, DIM_, biasqkv,
            0, 0, 0, 1, 1, 1);
    }

    // 4. area pooling (fp16 K and V)
    {
        dim3 g(BH_, 4);
        pool_kernel<<<g, 256>>>();
    }

    // 5. attention (bh-major grid)
    {
        dim3 g(4, BH_);
        attn_kernel<<<g, 256, AQOF + 2 * ASTG>>>();
    }

    // 6. combine partials
    combine_kernel<<<ROWS_ * DIM_ / 512, 256>>>();

    // 7. out = attn @ w_o + b_o  (bf16 3-term, full precision)
    {
        dim3 g(DIM_ / 128, ROWS_ / 128, 1);
        gemm128_kernel<<<g, 256, 2 * GSTG>>>(attn_hi, attn_lo, DIM_, woT_hi, woT_lo, DIM_,
                                             out, nullptr, nullptr, DIM_, DIM_, b_o,
                                             0, 0, 0, 0, 0, 0);
    }
}